// round 2
// baseline (speedup 1.0000x reference)
#include <cuda_runtime.h>
#include <cuda_bf16.h>
#include <math.h>

// ---------------------------------------------------------------------------
// ToyMoE: conv stack (5x conv3x3+relu+maxpool2) -> noisy_top_k gating (eval)
//         -> sparse top-2 expert MLPs -> gate-combined output + aux loss.
// Round 0: correct fp32 baseline. Conv fused (conv+bias+relu+pool), MoE sparse.
// ---------------------------------------------------------------------------

#define NB   256     // batch
#define DD   2048    // feature dim
#define HID  4096
#define OO   1024
#define EE   16

// -------------------- scratch (device globals; no allocs) ------------------
__device__ float g_a1[256 * 128 * 32 * 32];   // after layer1
__device__ float g_a2[256 * 256 * 16 * 16];   // after layer2
__device__ float g_a3[256 * 256 * 8 * 8];     // after layer3
__device__ float g_a4[256 * 512 * 4 * 4];     // after layer4
__device__ float g_feats[256 * 2048];         // after layer5 (== feats)
__device__ float g_logits[256 * 16];
__device__ int   g_ecnt[16];
__device__ int   g_etok[16 * 256];
__device__ float g_egate[16 * 256];
__device__ float g_h[16 * 256 * 4096];        // fc1 outputs per (expert,pos)
__device__ float g_o[16 * 256 * 1024];        // fc2 outputs per (expert,pos)

// ---------------------------------------------------------------------------
// Layer 1: CI=3, CO=128, 64x64 -> pooled 32x32. Spatial-tiled (4 tiles of 16x16
// pooled), 8 output channels per block.
// grid (256, 16, 4), 256 threads
// ---------------------------------------------------------------------------
__global__ void conv1_pool(const float* __restrict__ in,
                           const float* __restrict__ wgt,
                           const float* __restrict__ bias,
                           float* __restrict__ out) {
    const int H = 64, W = 64;
    __shared__ float s_in[3][34][34];
    __shared__ float s_w[8 * 27];

    const int n   = blockIdx.x;
    const int cb0 = blockIdx.y * 8;
    const int tile = blockIdx.z;
    const int ty = (tile / 2) * 16, tx = (tile % 2) * 16;  // pooled tile base
    const int tid = threadIdx.x;
    const int lph = tid / 16, lpw = tid % 16;

    const int r0 = 2 * ty - 1, c0 = 2 * tx - 1;
    for (int i = tid; i < 3 * 34 * 34; i += 256) {
        int ci = i / (34 * 34);
        int rr = (i / 34) % 34, cc = i % 34;
        int r = r0 + rr, c = c0 + cc;
        float v = 0.f;
        if (r >= 0 && r < H && c >= 0 && c < W)
            v = in[((n * 3 + ci) * H + r) * W + c];
        s_in[ci][rr][cc] = v;
    }
    for (int i = tid; i < 8 * 27; i += 256) s_w[i] = wgt[cb0 * 27 + i];
    __syncthreads();

    float acc[8][4];
    #pragma unroll
    for (int t = 0; t < 8; t++) { acc[t][0]=acc[t][1]=acc[t][2]=acc[t][3]=0.f; }

    #pragma unroll
    for (int ci = 0; ci < 3; ci++) {
        float win[16];
        #pragma unroll
        for (int r = 0; r < 4; r++)
            #pragma unroll
            for (int c = 0; c < 4; c++)
                win[r * 4 + c] = s_in[ci][2 * lph + r][2 * lpw + c];
        #pragma unroll
        for (int t = 0; t < 8; t++) {
            const float* wp = &s_w[t * 27 + ci * 9];
            float w0=wp[0],w1=wp[1],w2=wp[2],w3=wp[3],w4=wp[4],w5=wp[5],w6=wp[6],w7=wp[7],w8=wp[8];
            #pragma unroll
            for (int dy = 0; dy < 2; dy++)
                #pragma unroll
                for (int dx = 0; dx < 2; dx++) {
                    float s = win[(dy+0)*4 + dx+0]*w0 + win[(dy+0)*4 + dx+1]*w1 + win[(dy+0)*4 + dx+2]*w2
                            + win[(dy+1)*4 + dx+0]*w3 + win[(dy+1)*4 + dx+1]*w4 + win[(dy+1)*4 + dx+2]*w5
                            + win[(dy+2)*4 + dx+0]*w6 + win[(dy+2)*4 + dx+1]*w7 + win[(dy+2)*4 + dx+2]*w8;
                    acc[t][dy * 2 + dx] += s;
                }
        }
    }
    const int ph = ty + lph, pw = tx + lpw;
    #pragma unroll
    for (int t = 0; t < 8; t++) {
        int co = cb0 + t;
        float b = bias[co];
        float m = fmaxf(fmaxf(acc[t][0], acc[t][1]), fmaxf(acc[t][2], acc[t][3]));
        out[(((size_t)n * 128 + co) * 32 + ph) * 32 + pw] = fmaxf(m + b, 0.f);
    }
}

// ---------------------------------------------------------------------------
// Generic fused conv3x3+bias+relu+maxpool2 for layers 2..5 (full image per CTA)
// Block handles (n, COB=CO_T*CG channels). threads = (H/2)*(H/2)*CG.
// ---------------------------------------------------------------------------
template <int CI, int H, int CO_T, int CG>
__global__ void conv_pool_full(const float* __restrict__ in,
                               const float* __restrict__ wgt,
                               const float* __restrict__ bias,
                               float* __restrict__ out, int CO) {
    constexpr int W = H, P = H / 2, NPX = P * P;
    constexpr int COB = CO_T * CG;
    constexpr int HP = H + 2;
    constexpr int NT = NPX * CG;
    __shared__ float s_in[HP * HP];
    __shared__ float s_w[COB * 9];

    const int n   = blockIdx.x;
    const int cb0 = blockIdx.y * COB;
    const int tid = threadIdx.x;
    const int px  = tid % NPX;
    const int cg  = tid / NPX;
    const int ph = px / P, pw = px % P;
    const int co0 = cb0 + cg * CO_T;

    for (int i = tid; i < HP * HP; i += NT) s_in[i] = 0.f;   // halo zeros
    __syncthreads();

    float acc[CO_T][4];
    #pragma unroll
    for (int t = 0; t < CO_T; t++) { acc[t][0]=acc[t][1]=acc[t][2]=acc[t][3]=0.f; }

    const float* inN = in + (size_t)n * CI * H * W;
    for (int ci = 0; ci < CI; ci++) {
        const float* ip = inN + ci * H * W;
        for (int i = tid; i < H * W; i += NT) {
            int r = i / W, c = i % W;
            s_in[(r + 1) * HP + (c + 1)] = ip[i];
        }
        for (int i = tid; i < COB * 9; i += NT) {
            int j = i / 9, k = i % 9;
            s_w[i] = wgt[(size_t)(cb0 + j) * CI * 9 + ci * 9 + k];
        }
        __syncthreads();

        float win[16];
        #pragma unroll
        for (int r = 0; r < 4; r++)
            #pragma unroll
            for (int c = 0; c < 4; c++)
                win[r * 4 + c] = s_in[(2 * ph + r) * HP + (2 * pw + c)];
        #pragma unroll
        for (int t = 0; t < CO_T; t++) {
            const float* wp = &s_w[(cg * CO_T + t) * 9];
            float w0=wp[0],w1=wp[1],w2=wp[2],w3=wp[3],w4=wp[4],w5=wp[5],w6=wp[6],w7=wp[7],w8=wp[8];
            #pragma unroll
            for (int dy = 0; dy < 2; dy++)
                #pragma unroll
                for (int dx = 0; dx < 2; dx++) {
                    float s = win[(dy+0)*4 + dx+0]*w0 + win[(dy+0)*4 + dx+1]*w1 + win[(dy+0)*4 + dx+2]*w2
                            + win[(dy+1)*4 + dx+0]*w3 + win[(dy+1)*4 + dx+1]*w4 + win[(dy+1)*4 + dx+2]*w5
                            + win[(dy+2)*4 + dx+0]*w6 + win[(dy+2)*4 + dx+1]*w7 + win[(dy+2)*4 + dx+2]*w8;
                    acc[t][dy * 2 + dx] += s;
                }
        }
        __syncthreads();
    }
    #pragma unroll
    for (int t = 0; t < CO_T; t++) {
        int co = co0 + t;
        float b = bias[co];
        float m = fmaxf(fmaxf(acc[t][0], acc[t][1]), fmaxf(acc[t][2], acc[t][3]));
        out[(((size_t)n * CO + co) * P + ph) * P + pw] = fmaxf(m + b, 0.f);
    }
}

// ---------------------------------------------------------------------------
// Gating: logits = feats @ w_gate   (grid 256, 128 threads)
// ---------------------------------------------------------------------------
__global__ void gate_logits(const float* __restrict__ feats,
                            const float* __restrict__ wg,
                            float* __restrict__ logits) {
    const int b = blockIdx.x, tid = threadIdx.x;
    float acc[16];
    #pragma unroll
    for (int e = 0; e < 16; e++) acc[e] = 0.f;
    for (int d = tid; d < DD; d += 128) {
        float f = feats[(size_t)b * DD + d];
        const float* wr = wg + (size_t)d * 16;
        #pragma unroll
        for (int e = 0; e < 16; e++) acc[e] += f * wr[e];
    }
    __shared__ float sacc[128][16];
    #pragma unroll
    for (int e = 0; e < 16; e++) sacc[tid][e] = acc[e];
    __syncthreads();
    if (tid < 16) {
        float s = 0.f;
        for (int i = 0; i < 128; i++) s += sacc[i][tid];
        logits[b * 16 + tid] = s;
    }
}

// ---------------------------------------------------------------------------
// Top-2 gating + expert grouping + aux loss. Single block, 256 threads.
// Deterministic: lists & importance/load built sequentially by 16 threads.
// ---------------------------------------------------------------------------
__global__ void gate_topk(const float* __restrict__ logits,
                          int* __restrict__ ecnt, int* __restrict__ etok,
                          float* __restrict__ egate, float* __restrict__ out_aux) {
    __shared__ int   s_e1[256], s_e2[256];
    __shared__ float s_g1[256], s_g2[256];
    __shared__ float s_imp[16], s_load[16];
    const int tid = threadIdx.x;

    const float* lr = logits + tid * 16;
    float v1 = -1e30f; int i1 = 0;
    #pragma unroll
    for (int e = 0; e < 16; e++) { float v = lr[e]; if (v > v1) { v1 = v; i1 = e; } }
    float v2 = -1e30f; int i2 = 0;
    #pragma unroll
    for (int e = 0; e < 16; e++) { if (e == i1) continue; float v = lr[e]; if (v > v2) { v2 = v; i2 = e; } }
    float ex = expf(v2 - v1);
    float inv = 1.f / (1.f + ex);
    s_e1[tid] = i1; s_e2[tid] = i2;
    s_g1[tid] = inv; s_g2[tid] = ex * inv;
    __syncthreads();

    if (tid < 16) {
        int e = tid, cnt = 0; float imp = 0.f;
        for (int b = 0; b < 256; b++) {
            if (s_e1[b] == e && s_g1[b] > 0.f) {
                etok[e * 256 + cnt] = b; egate[e * 256 + cnt] = s_g1[b];
                cnt++; imp += s_g1[b];
            } else if (s_e2[b] == e && s_g2[b] > 0.f) {
                etok[e * 256 + cnt] = b; egate[e * 256 + cnt] = s_g2[b];
                cnt++; imp += s_g2[b];
            }
        }
        ecnt[e] = cnt; s_imp[e] = imp; s_load[e] = (float)cnt;
    }
    __syncthreads();
    if (tid == 0 && out_aux != nullptr) {
        float mi = 0.f, ml = 0.f;
        for (int e = 0; e < 16; e++) { mi += s_imp[e]; ml += s_load[e]; }
        mi /= 16.f; ml /= 16.f;
        float vi = 0.f, vl = 0.f;
        for (int e = 0; e < 16; e++) {
            float a = s_imp[e] - mi; vi += a * a;
            float b = s_load[e] - ml; vl += b * b;
        }
        vi /= 16.f; vl /= 16.f;
        *out_aux = 0.01f * (vi / (mi * mi + 1e-10f) + vl / (ml * ml + 1e-10f));
    }
}

// ---------------------------------------------------------------------------
// fc1: h = relu(feats @ w1[e] + b1[e]) per (expert, token-batch)
// grid (16, 8, 32), 128 threads, TB=8 tokens, HT=4 hid/thread (hid tile 512)
// ---------------------------------------------------------------------------
__global__ void moe_fc1(const float* __restrict__ feats,
                        const float* __restrict__ w1,
                        const float* __restrict__ b1,
                        const int* __restrict__ ecnt,
                        const int* __restrict__ etok,
                        float* __restrict__ hbuf) {
    constexpr int TB = 8, HT = 4;
    const int e = blockIdx.x;
    const int cnt = ecnt[e];
    const int t0 = blockIdx.z * TB;
    if (t0 >= cnt) return;
    const int tid = threadIdx.x;
    const int hid0 = blockIdx.y * 512 + tid;

    __shared__ float fch[TB][64];
    __shared__ int stok[TB];
    if (tid < TB) {
        int tt = t0 + tid; if (tt >= cnt) tt = cnt - 1;
        stok[tid] = etok[e * 256 + tt];
    }
    __syncthreads();

    float acc[TB][HT];
    #pragma unroll
    for (int j = 0; j < TB; j++)
        #pragma unroll
        for (int q = 0; q < HT; q++) acc[j][q] = 0.f;

    const float* w1e = w1 + (size_t)e * DD * HID;
    for (int dc = 0; dc < DD; dc += 64) {
        for (int i = tid; i < TB * 64; i += 128) {
            int j = i / 64, dd = i % 64;
            fch[j][dd] = feats[(size_t)stok[j] * DD + dc + dd];
        }
        __syncthreads();
        for (int dd = 0; dd < 64; dd++) {
            float wv[HT];
            const float* wrow = w1e + (size_t)(dc + dd) * HID + hid0;
            #pragma unroll
            for (int q = 0; q < HT; q++) wv[q] = wrow[q * 128];
            #pragma unroll
            for (int j = 0; j < TB; j++) {
                float f = fch[j][dd];
                #pragma unroll
                for (int q = 0; q < HT; q++) acc[j][q] += f * wv[q];
            }
        }
        __syncthreads();
    }
    float bias[HT];
    #pragma unroll
    for (int q = 0; q < HT; q++) bias[q] = b1[e * HID + hid0 + q * 128];
    for (int j = 0; j < TB; j++) {
        if (t0 + j >= cnt) break;
        size_t slot = (size_t)(e * 256 + t0 + j);
        #pragma unroll
        for (int q = 0; q < HT; q++)
            hbuf[slot * HID + hid0 + q * 128] = fmaxf(acc[j][q] + bias[q], 0.f);
    }
}

// ---------------------------------------------------------------------------
// fc2: o = h @ w2[e] + b2[e]     grid (16, 2, 32), 128 threads
// ---------------------------------------------------------------------------
__global__ void moe_fc2(const float* __restrict__ hbuf,
                        const float* __restrict__ w2,
                        const float* __restrict__ b2,
                        const int* __restrict__ ecnt,
                        float* __restrict__ obuf) {
    constexpr int TB = 8, HT = 4;
    const int e = blockIdx.x;
    const int cnt = ecnt[e];
    const int t0 = blockIdx.z * TB;
    if (t0 >= cnt) return;
    const int tid = threadIdx.x;
    const int o0 = blockIdx.y * 512 + tid;

    __shared__ float hch[TB][64];

    float acc[TB][HT];
    #pragma unroll
    for (int j = 0; j < TB; j++)
        #pragma unroll
        for (int q = 0; q < HT; q++) acc[j][q] = 0.f;

    const float* w2e = w2 + (size_t)e * HID * OO;
    for (int hc = 0; hc < HID; hc += 64) {
        for (int i = tid; i < TB * 64; i += 128) {
            int j = i / 64, dd = i % 64;
            int tt = t0 + j; if (tt >= cnt) tt = cnt - 1;
            hch[j][dd] = hbuf[(size_t)(e * 256 + tt) * HID + hc + dd];
        }
        __syncthreads();
        for (int dd = 0; dd < 64; dd++) {
            float wv[HT];
            const float* wrow = w2e + (size_t)(hc + dd) * OO + o0;
            #pragma unroll
            for (int q = 0; q < HT; q++) wv[q] = wrow[q * 128];
            #pragma unroll
            for (int j = 0; j < TB; j++) {
                float h = hch[j][dd];
                #pragma unroll
                for (int q = 0; q < HT; q++) acc[j][q] += h * wv[q];
            }
        }
        __syncthreads();
    }
    float bias[HT];
    #pragma unroll
    for (int q = 0; q < HT; q++) bias[q] = b2[e * OO + o0 + q * 128];
    for (int j = 0; j < TB; j++) {
        if (t0 + j >= cnt) break;
        size_t slot = (size_t)(e * 256 + t0 + j);
        #pragma unroll
        for (int q = 0; q < HT; q++)
            obuf[slot * OO + o0 + q * 128] = acc[j][q] + bias[q];
    }
}

// ---------------------------------------------------------------------------
// softmax over o row + gate-weighted accumulate into y. grid 4096, 256 threads
// y[b][o] receives exactly <=2 atomic adds onto 0 -> bitwise deterministic.
// ---------------------------------------------------------------------------
__global__ void moe_combine(const float* __restrict__ obuf,
                            const int* __restrict__ ecnt,
                            const float* __restrict__ egate,
                            const int* __restrict__ etok,
                            float* __restrict__ y) {
    const int e = blockIdx.x >> 8;
    const int pos = blockIdx.x & 255;
    if (pos >= ecnt[e]) return;
    const int slot = e * 256 + pos;
    const int tid = threadIdx.x;
    const float* orow = obuf + (size_t)slot * OO;

    float v[4];
    #pragma unroll
    for (int q = 0; q < 4; q++) v[q] = orow[tid + q * 256];

    __shared__ float red[256];
    float m4 = fmaxf(fmaxf(v[0], v[1]), fmaxf(v[2], v[3]));
    red[tid] = m4; __syncthreads();
    for (int s = 128; s > 0; s >>= 1) {
        if (tid < s) red[tid] = fmaxf(red[tid], red[tid + s]);
        __syncthreads();
    }
    float m = red[0]; __syncthreads();

    float ev[4];
    #pragma unroll
    for (int q = 0; q < 4; q++) ev[q] = expf(v[q] - m);
    red[tid] = ev[0] + ev[1] + ev[2] + ev[3]; __syncthreads();
    for (int s = 128; s > 0; s >>= 1) {
        if (tid < s) red[tid] += red[tid + s];
        __syncthreads();
    }
    float scale = egate[slot] / red[0];
    int b = etok[slot];
    #pragma unroll
    for (int q = 0; q < 4; q++)
        atomicAdd(&y[(size_t)b * OO + tid + q * 256], ev[q] * scale);
}

__global__ void zero_y(float* __restrict__ y) {
    int i = blockIdx.x * blockDim.x + threadIdx.x;
    if (i < NB * OO) y[i] = 0.f;
}

// ---------------------------------------------------------------------------
extern "C" void kernel_launch(void* const* d_in, const int* in_sizes, int n_in,
                              void* d_out, int out_size) {
    const float* x   = (const float*)d_in[0];
    const float* cw1 = (const float*)d_in[1];  const float* cb1 = (const float*)d_in[2];
    const float* cw2 = (const float*)d_in[3];  const float* cb2 = (const float*)d_in[4];
    const float* cw3 = (const float*)d_in[5];  const float* cb3 = (const float*)d_in[6];
    const float* cw4 = (const float*)d_in[7];  const float* cb4 = (const float*)d_in[8];
    const float* cw5 = (const float*)d_in[9];  const float* cb5 = (const float*)d_in[10];
    const float* w1  = (const float*)d_in[11]; const float* b1  = (const float*)d_in[12];
    const float* w2  = (const float*)d_in[13]; const float* b2  = (const float*)d_in[14];
    const float* wg  = (const float*)d_in[15];
    float* out = (float*)d_out;

    float *a1, *a2, *a3, *a4, *feats, *logits, *egate, *hbuf, *obuf;
    int *ecnt, *etok;
    cudaGetSymbolAddress((void**)&a1, g_a1);
    cudaGetSymbolAddress((void**)&a2, g_a2);
    cudaGetSymbolAddress((void**)&a3, g_a3);
    cudaGetSymbolAddress((void**)&a4, g_a4);
    cudaGetSymbolAddress((void**)&feats, g_feats);
    cudaGetSymbolAddress((void**)&logits, g_logits);
    cudaGetSymbolAddress((void**)&ecnt, g_ecnt);
    cudaGetSymbolAddress((void**)&etok, g_etok);
    cudaGetSymbolAddress((void**)&egate, g_egate);
    cudaGetSymbolAddress((void**)&hbuf, g_h);
    cudaGetSymbolAddress((void**)&obuf, g_o);

    float* aux_ptr = (out_size > NB * OO) ? (out + NB * OO) : nullptr;

    zero_y<<<(NB * OO + 255) / 256, 256>>>(out);

    conv1_pool<<<dim3(256, 16, 4), 256>>>(x, cw1, cb1, a1);
    conv_pool_full<128, 32, 8, 1><<<dim3(256, 32), 256>>>(a1, cw2, cb2, a2, 256);
    conv_pool_full<256, 16, 8, 4><<<dim3(256, 8), 256>>>(a2, cw3, cb3, a3, 256);
    conv_pool_full<256, 8, 8, 8><<<dim3(256, 8), 128>>>(a3, cw4, cb4, a4, 512);
    conv_pool_full<512, 4, 8, 32><<<dim3(256, 2), 128>>>(a4, cw5, cb5, feats, 512);

    gate_logits<<<256, 128>>>(feats, wg, logits);
    gate_topk<<<1, 256>>>(logits, ecnt, etok, egate, aux_ptr);

    moe_fc1<<<dim3(16, 8, 32), 128>>>(feats, w1, b1, ecnt, etok, hbuf);
    moe_fc2<<<dim3(16, 2, 32), 128>>>(hbuf, w2, b2, ecnt, obuf);
    moe_combine<<<dim3(16 * 256), 256>>>(obuf, ecnt, egate, etok, out);
}

// round 4
// speedup vs baseline: 1.0741x; 1.0741x over previous
#include <cuda_runtime.h>
#include <cuda_bf16.h>
#include <math.h>

// ---------------------------------------------------------------------------
// ToyMoE round 2: fp32 conv stack now uses packed fma.rn.f32x2 (FFMA2) —
// exact fp32 math, 2 FMAs per issued instruction. MoE path unchanged.
// ---------------------------------------------------------------------------

#define NB   256
#define DD   2048
#define HID  4096
#define OO   1024
#define EE   16

typedef unsigned long long u64;

__device__ __forceinline__ u64 pack2(float lo, float hi) {
    u64 r; asm("mov.b64 %0, {%1, %2};" : "=l"(r) : "f"(lo), "f"(hi)); return r;
}
__device__ __forceinline__ void unpack2(u64 v, float& lo, float& hi) {
    asm("mov.b64 {%0, %1}, %2;" : "=f"(lo), "=f"(hi) : "l"(v));
}
__device__ __forceinline__ u64 ffma2(u64 a, u64 b, u64 c) {
    u64 d; asm("fma.rn.f32x2 %0, %1, %2, %3;" : "=l"(d) : "l"(a), "l"(b), "l"(c));
    return d;
}

// -------------------- scratch (device globals; no allocs) ------------------
__device__ float g_a1[256 * 128 * 32 * 32];
__device__ float g_a2[256 * 256 * 16 * 16];
__device__ float g_a3[256 * 256 * 8 * 8];
__device__ float g_a4[256 * 512 * 4 * 4];
__device__ float g_feats[256 * 2048];
__device__ float g_logits[256 * 16];
__device__ int   g_ecnt[16];
__device__ int   g_etok[16 * 256];
__device__ float g_egate[16 * 256];
__device__ float g_h[16 * 256 * 4096];
__device__ float g_o[16 * 256 * 1024];

// ---------------------------------------------------------------------------
// Layer 1: CI=3, CO=128, 64x64 -> pooled 32x32. (small: left as scalar fp32)
// grid (256, 16, 4), 256 threads
// ---------------------------------------------------------------------------
__global__ void conv1_pool(const float* __restrict__ in,
                           const float* __restrict__ wgt,
                           const float* __restrict__ bias,
                           float* __restrict__ out) {
    const int H = 64, W = 64;
    __shared__ float s_in[3][34][34];
    __shared__ float s_w[8 * 27];

    const int n   = blockIdx.x;
    const int cb0 = blockIdx.y * 8;
    const int tile = blockIdx.z;
    const int ty = (tile / 2) * 16, tx = (tile % 2) * 16;
    const int tid = threadIdx.x;
    const int lph = tid / 16, lpw = tid % 16;

    const int r0 = 2 * ty - 1, c0 = 2 * tx - 1;
    for (int i = tid; i < 3 * 34 * 34; i += 256) {
        int ci = i / (34 * 34);
        int rr = (i / 34) % 34, cc = i % 34;
        int r = r0 + rr, c = c0 + cc;
        float v = 0.f;
        if (r >= 0 && r < H && c >= 0 && c < W)
            v = in[((n * 3 + ci) * H + r) * W + c];
        s_in[ci][rr][cc] = v;
    }
    for (int i = tid; i < 8 * 27; i += 256) s_w[i] = wgt[cb0 * 27 + i];
    __syncthreads();

    float acc[8][4];
    #pragma unroll
    for (int t = 0; t < 8; t++) { acc[t][0]=acc[t][1]=acc[t][2]=acc[t][3]=0.f; }

    #pragma unroll
    for (int ci = 0; ci < 3; ci++) {
        float win[16];
        #pragma unroll
        for (int r = 0; r < 4; r++)
            #pragma unroll
            for (int c = 0; c < 4; c++)
                win[r * 4 + c] = s_in[ci][2 * lph + r][2 * lpw + c];
        #pragma unroll
        for (int t = 0; t < 8; t++) {
            const float* wp = &s_w[t * 27 + ci * 9];
            float w0=wp[0],w1=wp[1],w2=wp[2],w3=wp[3],w4=wp[4],w5=wp[5],w6=wp[6],w7=wp[7],w8=wp[8];
            #pragma unroll
            for (int dy = 0; dy < 2; dy++)
                #pragma unroll
                for (int dx = 0; dx < 2; dx++) {
                    float s = win[(dy+0)*4 + dx+0]*w0 + win[(dy+0)*4 + dx+1]*w1 + win[(dy+0)*4 + dx+2]*w2
                            + win[(dy+1)*4 + dx+0]*w3 + win[(dy+1)*4 + dx+1]*w4 + win[(dy+1)*4 + dx+2]*w5
                            + win[(dy+2)*4 + dx+0]*w6 + win[(dy+2)*4 + dx+1]*w7 + win[(dy+2)*4 + dx+2]*w8;
                    acc[t][dy * 2 + dx] += s;
                }
        }
    }
    const int ph = ty + lph, pw = tx + lpw;
    #pragma unroll
    for (int t = 0; t < 8; t++) {
        int co = cb0 + t;
        float b = bias[co];
        float m = fmaxf(fmaxf(acc[t][0], acc[t][1]), fmaxf(acc[t][2], acc[t][3]));
        out[(((size_t)n * 128 + co) * 32 + ph) * 32 + pw] = fmaxf(m + b, 0.f);
    }
}

// ---------------------------------------------------------------------------
// Layers 2..5: fused conv3x3+bias+relu+maxpool2 using packed FFMA2.
// Pool dx-pair packed per accumulator: acc2[t][dy] = (out_dx0, out_dx1).
// Weights staged in smem pre-duplicated as (w,w) u64 pairs.
// ---------------------------------------------------------------------------
template <int CI, int H, int CO_T, int CG>
__global__ void __launch_bounds__((H/2)*(H/2)*CG)
conv_pool_full(const float* __restrict__ in,
               const float* __restrict__ wgt,
               const float* __restrict__ bias,
               float* __restrict__ out, int CO) {
    constexpr int W = H, P = H / 2, NPX = P * P;
    constexpr int COB = CO_T * CG;
    constexpr int HP = H + 2;
    constexpr int NT = NPX * CG;
    __shared__ float s_in[HP * HP];
    __shared__ u64  s_w2[COB * 10];       // 9 taps + pad, duplicated pairs

    const int n   = blockIdx.x;
    const int cb0 = blockIdx.y * COB;
    const int tid = threadIdx.x;
    const int px  = tid % NPX;
    const int cg  = tid / NPX;
    const int ph = px / P, pw = px % P;
    const int co0 = cb0 + cg * CO_T;

    for (int i = tid; i < HP * HP; i += NT) s_in[i] = 0.f;   // halo zeros
    __syncthreads();

    u64 acc2[CO_T][2];
    #pragma unroll
    for (int t = 0; t < CO_T; t++) { acc2[t][0] = 0ull; acc2[t][1] = 0ull; }

    const float* inN = in + (size_t)n * CI * H * W;
    for (int ci = 0; ci < CI; ci++) {
        const float* ip = inN + ci * H * W;
        if constexpr ((H * W) % (4 * NT) == 0) {
            // vectorized staging (conv2: one float4 per thread)
            for (int i = tid; i < (H * W) / 4; i += NT) {
                float4 v = reinterpret_cast<const float4*>(ip)[i];
                int r = (i * 4) / W, c = (i * 4) % W;
                float* dst = &s_in[(r + 1) * HP + (c + 1)];
                dst[0] = v.x; dst[1] = v.y; dst[2] = v.z; dst[3] = v.w;
            }
        } else {
            for (int i = tid; i < H * W; i += NT) {
                int r = i / W, c = i % W;
                s_in[(r + 1) * HP + (c + 1)] = ip[i];
            }
        }
        for (int i = tid; i < COB * 9; i += NT) {
            int j = i / 9, k = i % 9;
            float w = wgt[(size_t)(cb0 + j) * CI * 9 + ci * 9 + k];
            s_w2[j * 10 + k] = pack2(w, w);
        }
        __syncthreads();

        // window 4x4, packed horizontal pairs wp[row][c] = (win[c], win[c+1])
        float win[4][4];
        #pragma unroll
        for (int r = 0; r < 4; r++)
            #pragma unroll
            for (int c = 0; c < 4; c++)
                win[r][c] = s_in[(2 * ph + r) * HP + (2 * pw + c)];
        u64 wp[4][3];
        #pragma unroll
        for (int r = 0; r < 4; r++)
            #pragma unroll
            for (int c = 0; c < 3; c++)
                wp[r][c] = pack2(win[r][c], win[r][c + 1]);

        #pragma unroll
        for (int t = 0; t < CO_T; t++) {
            const u64* wt = &s_w2[(cg * CO_T + t) * 10];
            u64 w[9];
            #pragma unroll
            for (int k = 0; k < 9; k++) w[k] = wt[k];
            #pragma unroll
            for (int dy = 0; dy < 2; dy++)
                #pragma unroll
                for (int r = 0; r < 3; r++)
                    #pragma unroll
                    for (int c = 0; c < 3; c++)
                        acc2[t][dy] = ffma2(wp[dy + r][c], w[r * 3 + c], acc2[t][dy]);
        }
        __syncthreads();
    }
    #pragma unroll
    for (int t = 0; t < CO_T; t++) {
        int co = co0 + t;
        float b = bias[co];
        float a00, a01, a10, a11;
        unpack2(acc2[t][0], a00, a01);
        unpack2(acc2[t][1], a10, a11);
        float m = fmaxf(fmaxf(a00, a01), fmaxf(a10, a11));
        out[(((size_t)n * CO + co) * P + ph) * P + pw] = fmaxf(m + b, 0.f);
    }
}

// ---------------------------------------------------------------------------
// Gating: logits = feats @ w_gate   (grid 256, 128 threads)
// ---------------------------------------------------------------------------
__global__ void gate_logits(const float* __restrict__ feats,
                            const float* __restrict__ wg,
                            float* __restrict__ logits) {
    const int b = blockIdx.x, tid = threadIdx.x;
    float acc[16];
    #pragma unroll
    for (int e = 0; e < 16; e++) acc[e] = 0.f;
    for (int d = tid; d < DD; d += 128) {
        float f = feats[(size_t)b * DD + d];
        const float* wr = wg + (size_t)d * 16;
        #pragma unroll
        for (int e = 0; e < 16; e++) acc[e] += f * wr[e];
    }
    __shared__ float sacc[128][16];
    #pragma unroll
    for (int e = 0; e < 16; e++) sacc[tid][e] = acc[e];
    __syncthreads();
    if (tid < 16) {
        float s = 0.f;
        for (int i = 0; i < 128; i++) s += sacc[i][tid];
        logits[b * 16 + tid] = s;
    }
}

// ---------------------------------------------------------------------------
// Top-2 gating + expert grouping + aux loss. Single block, 256 threads.
// ---------------------------------------------------------------------------
__global__ void gate_topk(const float* __restrict__ logits,
                          int* __restrict__ ecnt, int* __restrict__ etok,
                          float* __restrict__ egate, float* __restrict__ out_aux) {
    __shared__ int   s_e1[256], s_e2[256];
    __shared__ float s_g1[256], s_g2[256];
    __shared__ float s_imp[16], s_load[16];
    const int tid = threadIdx.x;

    const float* lr = logits + tid * 16;
    float v1 = -1e30f; int i1 = 0;
    #pragma unroll
    for (int e = 0; e < 16; e++) { float v = lr[e]; if (v > v1) { v1 = v; i1 = e; } }
    float v2 = -1e30f; int i2 = 0;
    #pragma unroll
    for (int e = 0; e < 16; e++) { if (e == i1) continue; float v = lr[e]; if (v > v2) { v2 = v; i2 = e; } }
    float ex = expf(v2 - v1);
    float inv = 1.f / (1.f + ex);
    s_e1[tid] = i1; s_e2[tid] = i2;
    s_g1[tid] = inv; s_g2[tid] = ex * inv;
    __syncthreads();

    if (tid < 16) {
        int e = tid, cnt = 0; float imp = 0.f;
        for (int b = 0; b < 256; b++) {
            if (s_e1[b] == e && s_g1[b] > 0.f) {
                etok[e * 256 + cnt] = b; egate[e * 256 + cnt] = s_g1[b];
                cnt++; imp += s_g1[b];
            } else if (s_e2[b] == e && s_g2[b] > 0.f) {
                etok[e * 256 + cnt] = b; egate[e * 256 + cnt] = s_g2[b];
                cnt++; imp += s_g2[b];
            }
        }
        ecnt[e] = cnt; s_imp[e] = imp; s_load[e] = (float)cnt;
    }
    __syncthreads();
    if (tid == 0 && out_aux != nullptr) {
        float mi = 0.f, ml = 0.f;
        for (int e = 0; e < 16; e++) { mi += s_imp[e]; ml += s_load[e]; }
        mi /= 16.f; ml /= 16.f;
        float vi = 0.f, vl = 0.f;
        for (int e = 0; e < 16; e++) {
            float a = s_imp[e] - mi; vi += a * a;
            float b = s_load[e] - ml; vl += b * b;
        }
        vi /= 16.f; vl /= 16.f;
        *out_aux = 0.01f * (vi / (mi * mi + 1e-10f) + vl / (ml * ml + 1e-10f));
    }
}

// ---------------------------------------------------------------------------
// fc1: h = relu(feats @ w1[e] + b1[e])  grid (16, 8, 32), 128 threads
// ---------------------------------------------------------------------------
__global__ void moe_fc1(const float* __restrict__ feats,
                        const float* __restrict__ w1,
                        const float* __restrict__ b1,
                        const int* __restrict__ ecnt,
                        const int* __restrict__ etok,
                        float* __restrict__ hbuf) {
    constexpr int TB = 8, HT = 4;
    const int e = blockIdx.x;
    const int cnt = ecnt[e];
    const int t0 = blockIdx.z * TB;
    if (t0 >= cnt) return;
    const int tid = threadIdx.x;
    const int hid0 = blockIdx.y * 512 + tid;

    __shared__ float fch[TB][64];
    __shared__ int stok[TB];
    if (tid < TB) {
        int tt = t0 + tid; if (tt >= cnt) tt = cnt - 1;
        stok[tid] = etok[e * 256 + tt];
    }
    __syncthreads();

    float acc[TB][HT];
    #pragma unroll
    for (int j = 0; j < TB; j++)
        #pragma unroll
        for (int q = 0; q < HT; q++) acc[j][q] = 0.f;

    const float* w1e = w1 + (size_t)e * DD * HID;
    for (int dc = 0; dc < DD; dc += 64) {
        for (int i = tid; i < TB * 64; i += 128) {
            int j = i / 64, dd = i % 64;
            fch[j][dd] = feats[(size_t)stok[j] * DD + dc + dd];
        }
        __syncthreads();
        for (int dd = 0; dd < 64; dd++) {
            float wv[HT];
            const float* wrow = w1e + (size_t)(dc + dd) * HID + hid0;
            #pragma unroll
            for (int q = 0; q < HT; q++) wv[q] = wrow[q * 128];
            #pragma unroll
            for (int j = 0; j < TB; j++) {
                float f = fch[j][dd];
                #pragma unroll
                for (int q = 0; q < HT; q++) acc[j][q] += f * wv[q];
            }
        }
        __syncthreads();
    }
    float bias[HT];
    #pragma unroll
    for (int q = 0; q < HT; q++) bias[q] = b1[e * HID + hid0 + q * 128];
    for (int j = 0; j < TB; j++) {
        if (t0 + j >= cnt) break;
        size_t slot = (size_t)(e * 256 + t0 + j);
        #pragma unroll
        for (int q = 0; q < HT; q++)
            hbuf[slot * HID + hid0 + q * 128] = fmaxf(acc[j][q] + bias[q], 0.f);
    }
}

// ---------------------------------------------------------------------------
// fc2: o = h @ w2[e] + b2[e]     grid (16, 2, 32), 128 threads
// ---------------------------------------------------------------------------
__global__ void moe_fc2(const float* __restrict__ hbuf,
                        const float* __restrict__ w2,
                        const float* __restrict__ b2,
                        const int* __restrict__ ecnt,
                        float* __restrict__ obuf) {
    constexpr int TB = 8, HT = 4;
    const int e = blockIdx.x;
    const int cnt = ecnt[e];
    const int t0 = blockIdx.z * TB;
    if (t0 >= cnt) return;
    const int tid = threadIdx.x;
    const int o0 = blockIdx.y * 512 + tid;

    __shared__ float hch[TB][64];

    float acc[TB][HT];
    #pragma unroll
    for (int j = 0; j < TB; j++)
        #pragma unroll
        for (int q = 0; q < HT; q++) acc[j][q] = 0.f;

    const float* w2e = w2 + (size_t)e * HID * OO;
    for (int hc = 0; hc < HID; hc += 64) {
        for (int i = tid; i < TB * 64; i += 128) {
            int j = i / 64, dd = i % 64;
            int tt = t0 + j; if (tt >= cnt) tt = cnt - 1;
            hch[j][dd] = hbuf[(size_t)(e * 256 + tt) * HID + hc + dd];
        }
        __syncthreads();
        for (int dd = 0; dd < 64; dd++) {
            float wv[HT];
            const float* wrow = w2e + (size_t)(hc + dd) * OO + o0;
            #pragma unroll
            for (int q = 0; q < HT; q++) wv[q] = wrow[q * 128];
            #pragma unroll
            for (int j = 0; j < TB; j++) {
                float h = hch[j][dd];
                #pragma unroll
                for (int q = 0; q < HT; q++) acc[j][q] += h * wv[q];
            }
        }
        __syncthreads();
    }
    float bias[HT];
    #pragma unroll
    for (int q = 0; q < HT; q++) bias[q] = b2[e * OO + o0 + q * 128];
    for (int j = 0; j < TB; j++) {
        if (t0 + j >= cnt) break;
        size_t slot = (size_t)(e * 256 + t0 + j);
        #pragma unroll
        for (int q = 0; q < HT; q++)
            obuf[slot * OO + o0 + q * 128] = acc[j][q] + bias[q];
    }
}

// ---------------------------------------------------------------------------
// softmax over o row + gate-weighted accumulate into y. grid 4096, 256 threads
// ---------------------------------------------------------------------------
__global__ void moe_combine(const float* __restrict__ obuf,
                            const int* __restrict__ ecnt,
                            const float* __restrict__ egate,
                            const int* __restrict__ etok,
                            float* __restrict__ y) {
    const int e = blockIdx.x >> 8;
    const int pos = blockIdx.x & 255;
    if (pos >= ecnt[e]) return;
    const int slot = e * 256 + pos;
    const int tid = threadIdx.x;
    const float* orow = obuf + (size_t)slot * OO;

    float v[4];
    #pragma unroll
    for (int q = 0; q < 4; q++) v[q] = orow[tid + q * 256];

    __shared__ float red[256];
    float m4 = fmaxf(fmaxf(v[0], v[1]), fmaxf(v[2], v[3]));
    red[tid] = m4; __syncthreads();
    for (int s = 128; s > 0; s >>= 1) {
        if (tid < s) red[tid] = fmaxf(red[tid], red[tid + s]);
        __syncthreads();
    }
    float m = red[0]; __syncthreads();

    float ev[4];
    #pragma unroll
    for (int q = 0; q < 4; q++) ev[q] = expf(v[q] - m);
    red[tid] = ev[0] + ev[1] + ev[2] + ev[3]; __syncthreads();
    for (int s = 128; s > 0; s >>= 1) {
        if (tid < s) red[tid] += red[tid + s];
        __syncthreads();
    }
    float scale = egate[slot] / red[0];
    int b = etok[slot];
    #pragma unroll
    for (int q = 0; q < 4; q++)
        atomicAdd(&y[(size_t)b * OO + tid + q * 256], ev[q] * scale);
}

__global__ void zero_y(float* __restrict__ y) {
    int i = blockIdx.x * blockDim.x + threadIdx.x;
    if (i < NB * OO) y[i] = 0.f;
}

// ---------------------------------------------------------------------------
extern "C" void kernel_launch(void* const* d_in, const int* in_sizes, int n_in,
                              void* d_out, int out_size) {
    const float* x   = (const float*)d_in[0];
    const float* cw1 = (const float*)d_in[1];  const float* cb1 = (const float*)d_in[2];
    const float* cw2 = (const float*)d_in[3];  const float* cb2 = (const float*)d_in[4];
    const float* cw3 = (const float*)d_in[5];  const float* cb3 = (const float*)d_in[6];
    const float* cw4 = (const float*)d_in[7];  const float* cb4 = (const float*)d_in[8];
    const float* cw5 = (const float*)d_in[9];  const float* cb5 = (const float*)d_in[10];
    const float* w1  = (const float*)d_in[11]; const float* b1  = (const float*)d_in[12];
    const float* w2  = (const float*)d_in[13]; const float* b2  = (const float*)d_in[14];
    const float* wg  = (const float*)d_in[15];
    float* out = (float*)d_out;

    float *a1, *a2, *a3, *a4, *feats, *logits, *egate, *hbuf, *obuf;
    int *ecnt, *etok;
    cudaGetSymbolAddress((void**)&a1, g_a1);
    cudaGetSymbolAddress((void**)&a2, g_a2);
    cudaGetSymbolAddress((void**)&a3, g_a3);
    cudaGetSymbolAddress((void**)&a4, g_a4);
    cudaGetSymbolAddress((void**)&feats, g_feats);
    cudaGetSymbolAddress((void**)&logits, g_logits);
    cudaGetSymbolAddress((void**)&ecnt, g_ecnt);
    cudaGetSymbolAddress((void**)&etok, g_etok);
    cudaGetSymbolAddress((void**)&egate, g_egate);
    cudaGetSymbolAddress((void**)&hbuf, g_h);
    cudaGetSymbolAddress((void**)&obuf, g_o);

    float* aux_ptr = (out_size > NB * OO) ? (out + NB * OO) : nullptr;

    zero_y<<<(NB * OO + 255) / 256, 256>>>(out);

    conv1_pool<<<dim3(256, 16, 4), 256>>>(x, cw1, cb1, a1);
    conv_pool_full<128, 32, 8, 1><<<dim3(256, 32), 256>>>(a1, cw2, cb2, a2, 256);
    conv_pool_full<256, 16, 8, 4><<<dim3(256, 8), 256>>>(a2, cw3, cb3, a3, 256);
    conv_pool_full<256, 8, 8, 8><<<dim3(256, 8), 128>>>(a3, cw4, cb4, a4, 512);
    conv_pool_full<512, 4, 8, 32><<<dim3(256, 2), 128>>>(a4, cw5, cb5, feats, 512);

    gate_logits<<<256, 128>>>(feats, wg, logits);
    gate_topk<<<1, 256>>>(logits, ecnt, etok, egate, aux_ptr);

    moe_fc1<<<dim3(16, 8, 32), 128>>>(feats, w1, b1, ecnt, etok, hbuf);
    moe_fc2<<<dim3(16, 2, 32), 128>>>(hbuf, w2, b2, ecnt, obuf);
    moe_combine<<<dim3(16 * 256), 256>>>(obuf, ecnt, egate, etok, out);
}

// round 6
// speedup vs baseline: 1.1138x; 1.0370x over previous
#include <cuda_runtime.h>
#include <cuda_bf16.h>
#include <math.h>

// ---------------------------------------------------------------------------
// ToyMoE round 5: FFMA2-dense conv stack. Each thread: 2x2 pooled block
// (4x4 pre-pool) x CO_T=4 channels -> 288 FFMA2 per ci per thread vs
// 54 LDS.64. ci chunked by 2 (halves barriers). MoE path unchanged.
// ---------------------------------------------------------------------------

#define NB   256
#define DD   2048
#define HID  4096
#define OO   1024
#define EE   16

typedef unsigned long long u64;

__device__ __forceinline__ u64 pack2(float lo, float hi) {
    u64 r; asm("mov.b64 %0, {%1, %2};" : "=l"(r) : "f"(lo), "f"(hi)); return r;
}
__device__ __forceinline__ void unpack2(u64 v, float& lo, float& hi) {
    asm("mov.b64 {%0, %1}, %2;" : "=f"(lo), "=f"(hi) : "l"(v));
}
__device__ __forceinline__ u64 ffma2(u64 a, u64 b, u64 c) {
    u64 d; asm("fma.rn.f32x2 %0, %1, %2, %3;" : "=l"(d) : "l"(a), "l"(b), "l"(c));
    return d;
}

// -------------------- scratch (device globals; no allocs) ------------------
__device__ float g_a1[256 * 128 * 32 * 32];
__device__ float g_a2[256 * 256 * 16 * 16];
__device__ float g_a3[256 * 256 * 8 * 8];
__device__ float g_a4[256 * 512 * 4 * 4];
__device__ float g_feats[256 * 2048];
__device__ float g_logits[256 * 16];
__device__ int   g_ecnt[16];
__device__ int   g_etok[16 * 256];
__device__ float g_egate[16 * 256];
__device__ float g_h[16 * 256 * 4096];
__device__ float g_o[16 * 256 * 1024];

// ---------------------------------------------------------------------------
// Layer 1: CI=3, CO=128, 64x64 -> pooled 32x32. grid (256, 16, 4), 256 thr.
// ---------------------------------------------------------------------------
__global__ void conv1_pool(const float* __restrict__ in,
                           const float* __restrict__ wgt,
                           const float* __restrict__ bias,
                           float* __restrict__ out) {
    const int H = 64, W = 64;
    __shared__ float s_in[3][34][34];
    __shared__ float s_w[8 * 27];

    const int n   = blockIdx.x;
    const int cb0 = blockIdx.y * 8;
    const int tile = blockIdx.z;
    const int ty = (tile / 2) * 16, tx = (tile % 2) * 16;
    const int tid = threadIdx.x;
    const int lph = tid / 16, lpw = tid % 16;

    const int r0 = 2 * ty - 1, c0 = 2 * tx - 1;
    for (int i = tid; i < 3 * 34 * 34; i += 256) {
        int ci = i / (34 * 34);
        int rr = (i / 34) % 34, cc = i % 34;
        int r = r0 + rr, c = c0 + cc;
        float v = 0.f;
        if (r >= 0 && r < H && c >= 0 && c < W)
            v = in[((n * 3 + ci) * H + r) * W + c];
        s_in[ci][rr][cc] = v;
    }
    for (int i = tid; i < 8 * 27; i += 256) s_w[i] = wgt[cb0 * 27 + i];
    __syncthreads();

    float acc[8][4];
    #pragma unroll
    for (int t = 0; t < 8; t++) { acc[t][0]=acc[t][1]=acc[t][2]=acc[t][3]=0.f; }

    #pragma unroll
    for (int ci = 0; ci < 3; ci++) {
        float win[16];
        #pragma unroll
        for (int r = 0; r < 4; r++)
            #pragma unroll
            for (int c = 0; c < 4; c++)
                win[r * 4 + c] = s_in[ci][2 * lph + r][2 * lpw + c];
        #pragma unroll
        for (int t = 0; t < 8; t++) {
            const float* wp = &s_w[t * 27 + ci * 9];
            float w0=wp[0],w1=wp[1],w2=wp[2],w3=wp[3],w4=wp[4],w5=wp[5],w6=wp[6],w7=wp[7],w8=wp[8];
            #pragma unroll
            for (int dy = 0; dy < 2; dy++)
                #pragma unroll
                for (int dx = 0; dx < 2; dx++) {
                    float s = win[(dy+0)*4 + dx+0]*w0 + win[(dy+0)*4 + dx+1]*w1 + win[(dy+0)*4 + dx+2]*w2
                            + win[(dy+1)*4 + dx+0]*w3 + win[(dy+1)*4 + dx+1]*w4 + win[(dy+1)*4 + dx+2]*w5
                            + win[(dy+2)*4 + dx+0]*w6 + win[(dy+2)*4 + dx+1]*w7 + win[(dy+2)*4 + dx+2]*w8;
                    acc[t][dy * 2 + dx] += s;
                }
        }
    }
    const int ph = ty + lph, pw = tx + lpw;
    #pragma unroll
    for (int t = 0; t < 8; t++) {
        int co = cb0 + t;
        float b = bias[co];
        float m = fmaxf(fmaxf(acc[t][0], acc[t][1]), fmaxf(acc[t][2], acc[t][3]));
        out[(((size_t)n * 128 + co) * 32 + ph) * 32 + pw] = fmaxf(m + b, 0.f);
    }
}

// ---------------------------------------------------------------------------
// Layers 2..5: FFMA2-dense fused conv3x3+bias+relu+maxpool2.
// Thread tile: 2x2 pooled (4x4 pre-pool) x CO_T channels.
// CTA: IMG images x NBLK pooled-blocks x CG channel groups = 128 threads.
// ci chunked by 2: stage 2 channels -> bar -> compute both -> bar.
// Accumulation order per output identical to previous rounds.
// ---------------------------------------------------------------------------
template <int CI, int H, int IMG, int CG, int CO_T, int LGW>
__global__ void __launch_bounds__(128)
conv_pool2(const float* __restrict__ in,
           const float* __restrict__ wgt,
           const float* __restrict__ bias,
           float* __restrict__ out, int CO) {
    constexpr int W = H, HW = H * W, LG_HW = 2 * LGW;
    constexpr int P = H / 2, PB = P / 2, NBLK = PB * PB;
    constexpr int SP = H + 2, HPAD = H + 2, PLANE = HPAD * SP;
    constexpr int NT = IMG * NBLK * CG;
    constexpr int COB = CG * CO_T;
    static_assert(NT == 128, "128 threads expected");

    __shared__ float s_in[2][IMG * PLANE];
    __shared__ u64  s_w2[2][COB * 9];

    const int n0  = blockIdx.x * IMG;
    const int cb0 = blockIdx.y * COB;
    const int tid = threadIdx.x;
    const int b   = tid % NBLK;
    const int j   = (tid / NBLK) % IMG;
    const int cg  = tid / (NBLK * IMG);
    const int bx  = b % PB, by = b / PB;

    // zero whole input buffers once (halo stays zero; interior overwritten)
    for (int i = tid; i < IMG * PLANE; i += NT) { s_in[0][i] = 0.f; s_in[1][i] = 0.f; }
    __syncthreads();

    u64 acc[CO_T][4][2];
    #pragma unroll
    for (int t = 0; t < CO_T; t++)
        #pragma unroll
        for (int dy = 0; dy < 4; dy++) { acc[t][dy][0] = 0ull; acc[t][dy][1] = 0ull; }

    for (int cc0 = 0; cc0 < CI; cc0 += 2) {
        // ---- stage 2 channels (interior + packed weights) ----
        #pragma unroll
        for (int c = 0; c < 2; c++) {
            const int ci = cc0 + c;
            const float* ip = in + (size_t)n0 * CI * HW + (size_t)ci * HW;
            for (int i = tid; i < IMG * HW; i += NT) {
                int jj = i >> LG_HW;
                int rest = i & (HW - 1);
                int r = rest >> LGW, cx = rest & (W - 1);
                s_in[c][jj * PLANE + (r + 1) * SP + cx + 1] =
                    ip[(size_t)jj * CI * HW + rest];
            }
            for (int i = tid; i < COB * 9; i += NT) {
                float wv = wgt[(size_t)(cb0 + i / 9) * CI * 9 + ci * 9 + (i % 9)];
                s_w2[c][i] = pack2(wv, wv);
            }
        }
        __syncthreads();

        // ---- compute both channels ----
        #pragma unroll
        for (int c = 0; c < 2; c++) {
            u64 w[CO_T][9];
            #pragma unroll
            for (int t = 0; t < CO_T; t++)
                #pragma unroll
                for (int k = 0; k < 9; k++)
                    w[t][k] = s_w2[c][(cg * CO_T + t) * 9 + k];

            const float* base = &s_in[c][j * PLANE + (4 * by) * SP + 4 * bx];
            #pragma unroll
            for (int wr = 0; wr < 6; wr++) {
                // 6 consecutive floats as 3 aligned LDS.64 (row*SP+4bx is even)
                const u64* rp = (const u64*)(base + wr * SP);
                u64 wp[5];
                wp[0] = rp[0]; wp[2] = rp[1]; wp[4] = rp[2];
                float f0, f1, f2, f3, f4, f5;
                unpack2(wp[0], f0, f1); unpack2(wp[2], f2, f3); unpack2(wp[4], f4, f5);
                wp[1] = pack2(f1, f2); wp[3] = pack2(f3, f4);

                #pragma unroll
                for (int dy = 0; dy < 4; dy++) {
                    if (wr - dy < 0 || wr - dy > 2) continue;
                    const int kr = wr - dy;
                    #pragma unroll
                    for (int t = 0; t < CO_T; t++)
                        #pragma unroll
                        for (int cc = 0; cc < 3; cc++) {
                            acc[t][dy][0] = ffma2(wp[cc],     w[t][kr * 3 + cc], acc[t][dy][0]);
                            acc[t][dy][1] = ffma2(wp[2 + cc], w[t][kr * 3 + cc], acc[t][dy][1]);
                        }
                }
            }
        }
        __syncthreads();
    }

    // ---- epilogue: maxpool 2x2 + bias + relu ----
    #pragma unroll
    for (int t = 0; t < CO_T; t++) {
        const int co = cb0 + cg * CO_T + t;
        const float bv = bias[co];
        float v[4][4];
        #pragma unroll
        for (int dy = 0; dy < 4; dy++) {
            unpack2(acc[t][dy][0], v[dy][0], v[dy][1]);
            unpack2(acc[t][dy][1], v[dy][2], v[dy][3]);
        }
        #pragma unroll
        for (int py = 0; py < 2; py++)
            #pragma unroll
            for (int px = 0; px < 2; px++) {
                float m = fmaxf(fmaxf(v[2*py][2*px], v[2*py][2*px+1]),
                                fmaxf(v[2*py+1][2*px], v[2*py+1][2*px+1]));
                out[(((size_t)(n0 + j) * CO + co) * P + (2 * by + py)) * P + (2 * bx + px)]
                    = fmaxf(m + bv, 0.f);
            }
    }
}

// ---------------------------------------------------------------------------
// Gating: logits = feats @ w_gate   (grid 256, 128 threads)
// ---------------------------------------------------------------------------
__global__ void gate_logits(const float* __restrict__ feats,
                            const float* __restrict__ wg,
                            float* __restrict__ logits) {
    const int b = blockIdx.x, tid = threadIdx.x;
    float acc[16];
    #pragma unroll
    for (int e = 0; e < 16; e++) acc[e] = 0.f;
    for (int d = tid; d < DD; d += 128) {
        float f = feats[(size_t)b * DD + d];
        const float* wr = wg + (size_t)d * 16;
        #pragma unroll
        for (int e = 0; e < 16; e++) acc[e] += f * wr[e];
    }
    __shared__ float sacc[128][16];
    #pragma unroll
    for (int e = 0; e < 16; e++) sacc[tid][e] = acc[e];
    __syncthreads();
    if (tid < 16) {
        float s = 0.f;
        for (int i = 0; i < 128; i++) s += sacc[i][tid];
        logits[b * 16 + tid] = s;
    }
}

// ---------------------------------------------------------------------------
// Top-2 gating + expert grouping + aux loss. Single block, 256 threads.
// ---------------------------------------------------------------------------
__global__ void gate_topk(const float* __restrict__ logits,
                          int* __restrict__ ecnt, int* __restrict__ etok,
                          float* __restrict__ egate, float* __restrict__ out_aux) {
    __shared__ int   s_e1[256], s_e2[256];
    __shared__ float s_g1[256], s_g2[256];
    __shared__ float s_imp[16], s_load[16];
    const int tid = threadIdx.x;

    const float* lr = logits + tid * 16;
    float v1 = -1e30f; int i1 = 0;
    #pragma unroll
    for (int e = 0; e < 16; e++) { float v = lr[e]; if (v > v1) { v1 = v; i1 = e; } }
    float v2 = -1e30f; int i2 = 0;
    #pragma unroll
    for (int e = 0; e < 16; e++) { if (e == i1) continue; float v = lr[e]; if (v > v2) { v2 = v; i2 = e; } }
    float ex = expf(v2 - v1);
    float inv = 1.f / (1.f + ex);
    s_e1[tid] = i1; s_e2[tid] = i2;
    s_g1[tid] = inv; s_g2[tid] = ex * inv;
    __syncthreads();

    if (tid < 16) {
        int e = tid, cnt = 0; float imp = 0.f;
        for (int b = 0; b < 256; b++) {
            if (s_e1[b] == e && s_g1[b] > 0.f) {
                etok[e * 256 + cnt] = b; egate[e * 256 + cnt] = s_g1[b];
                cnt++; imp += s_g1[b];
            } else if (s_e2[b] == e && s_g2[b] > 0.f) {
                etok[e * 256 + cnt] = b; egate[e * 256 + cnt] = s_g2[b];
                cnt++; imp += s_g2[b];
            }
        }
        ecnt[e] = cnt; s_imp[e] = imp; s_load[e] = (float)cnt;
    }
    __syncthreads();
    if (tid == 0 && out_aux != nullptr) {
        float mi = 0.f, ml = 0.f;
        for (int e = 0; e < 16; e++) { mi += s_imp[e]; ml += s_load[e]; }
        mi /= 16.f; ml /= 16.f;
        float vi = 0.f, vl = 0.f;
        for (int e = 0; e < 16; e++) {
            float a = s_imp[e] - mi; vi += a * a;
            float b = s_load[e] - ml; vl += b * b;
        }
        vi /= 16.f; vl /= 16.f;
        *out_aux = 0.01f * (vi / (mi * mi + 1e-10f) + vl / (ml * ml + 1e-10f));
    }
}

// ---------------------------------------------------------------------------
// fc1: h = relu(feats @ w1[e] + b1[e])  grid (16, 8, 32), 128 threads
// ---------------------------------------------------------------------------
__global__ void moe_fc1(const float* __restrict__ feats,
                        const float* __restrict__ w1,
                        const float* __restrict__ b1,
                        const int* __restrict__ ecnt,
                        const int* __restrict__ etok,
                        float* __restrict__ hbuf) {
    constexpr int TB = 8, HT = 4;
    const int e = blockIdx.x;
    const int cnt = ecnt[e];
    const int t0 = blockIdx.z * TB;
    if (t0 >= cnt) return;
    const int tid = threadIdx.x;
    const int hid0 = blockIdx.y * 512 + tid;

    __shared__ float fch[TB][64];
    __shared__ int stok[TB];
    if (tid < TB) {
        int tt = t0 + tid; if (tt >= cnt) tt = cnt - 1;
        stok[tid] = etok[e * 256 + tt];
    }
    __syncthreads();

    float acc[TB][HT];
    #pragma unroll
    for (int j = 0; j < TB; j++)
        #pragma unroll
        for (int q = 0; q < HT; q++) acc[j][q] = 0.f;

    const float* w1e = w1 + (size_t)e * DD * HID;
    for (int dc = 0; dc < DD; dc += 64) {
        for (int i = tid; i < TB * 64; i += 128) {
            int j = i / 64, dd = i % 64;
            fch[j][dd] = feats[(size_t)stok[j] * DD + dc + dd];
        }
        __syncthreads();
        for (int dd = 0; dd < 64; dd++) {
            float wv[HT];
            const float* wrow = w1e + (size_t)(dc + dd) * HID + hid0;
            #pragma unroll
            for (int q = 0; q < HT; q++) wv[q] = wrow[q * 128];
            #pragma unroll
            for (int j = 0; j < TB; j++) {
                float f = fch[j][dd];
                #pragma unroll
                for (int q = 0; q < HT; q++) acc[j][q] += f * wv[q];
            }
        }
        __syncthreads();
    }
    float bias[HT];
    #pragma unroll
    for (int q = 0; q < HT; q++) bias[q] = b1[e * HID + hid0 + q * 128];
    for (int j = 0; j < TB; j++) {
        if (t0 + j >= cnt) break;
        size_t slot = (size_t)(e * 256 + t0 + j);
        #pragma unroll
        for (int q = 0; q < HT; q++)
            hbuf[slot * HID + hid0 + q * 128] = fmaxf(acc[j][q] + bias[q], 0.f);
    }
}

// ---------------------------------------------------------------------------
// fc2: o = h @ w2[e] + b2[e]     grid (16, 2, 32), 128 threads
// ---------------------------------------------------------------------------
__global__ void moe_fc2(const float* __restrict__ hbuf,
                        const float* __restrict__ w2,
                        const float* __restrict__ b2,
                        const int* __restrict__ ecnt,
                        float* __restrict__ obuf) {
    constexpr int TB = 8, HT = 4;
    const int e = blockIdx.x;
    const int cnt = ecnt[e];
    const int t0 = blockIdx.z * TB;
    if (t0 >= cnt) return;
    const int tid = threadIdx.x;
    const int o0 = blockIdx.y * 512 + tid;

    __shared__ float hch[TB][64];

    float acc[TB][HT];
    #pragma unroll
    for (int j = 0; j < TB; j++)
        #pragma unroll
        for (int q = 0; q < HT; q++) acc[j][q] = 0.f;

    const float* w2e = w2 + (size_t)e * HID * OO;
    for (int hc = 0; hc < HID; hc += 64) {
        for (int i = tid; i < TB * 64; i += 128) {
            int j = i / 64, dd = i % 64;
            int tt = t0 + j; if (tt >= cnt) tt = cnt - 1;
            hch[j][dd] = hbuf[(size_t)(e * 256 + tt) * HID + hc + dd];
        }
        __syncthreads();
        for (int dd = 0; dd < 64; dd++) {
            float wv[HT];
            const float* wrow = w2e + (size_t)(hc + dd) * OO + o0;
            #pragma unroll
            for (int q = 0; q < HT; q++) wv[q] = wrow[q * 128];
            #pragma unroll
            for (int j = 0; j < TB; j++) {
                float h = hch[j][dd];
                #pragma unroll
                for (int q = 0; q < HT; q++) acc[j][q] += h * wv[q];
            }
        }
        __syncthreads();
    }
    float bias[HT];
    #pragma unroll
    for (int q = 0; q < HT; q++) bias[q] = b2[e * OO + o0 + q * 128];
    for (int j = 0; j < TB; j++) {
        if (t0 + j >= cnt) break;
        size_t slot = (size_t)(e * 256 + t0 + j);
        #pragma unroll
        for (int q = 0; q < HT; q++)
            obuf[slot * OO + o0 + q * 128] = acc[j][q] + bias[q];
    }
}

// ---------------------------------------------------------------------------
// softmax over o row + gate-weighted accumulate into y. grid 4096, 256 threads
// ---------------------------------------------------------------------------
__global__ void moe_combine(const float* __restrict__ obuf,
                            const int* __restrict__ ecnt,
                            const float* __restrict__ egate,
                            const int* __restrict__ etok,
                            float* __restrict__ y) {
    const int e = blockIdx.x >> 8;
    const int pos = blockIdx.x & 255;
    if (pos >= ecnt[e]) return;
    const int slot = e * 256 + pos;
    const int tid = threadIdx.x;
    const float* orow = obuf + (size_t)slot * OO;

    float v[4];
    #pragma unroll
    for (int q = 0; q < 4; q++) v[q] = orow[tid + q * 256];

    __shared__ float red[256];
    float m4 = fmaxf(fmaxf(v[0], v[1]), fmaxf(v[2], v[3]));
    red[tid] = m4; __syncthreads();
    for (int s = 128; s > 0; s >>= 1) {
        if (tid < s) red[tid] = fmaxf(red[tid], red[tid + s]);
        __syncthreads();
    }
    float m = red[0]; __syncthreads();

    float ev[4];
    #pragma unroll
    for (int q = 0; q < 4; q++) ev[q] = expf(v[q] - m);
    red[tid] = ev[0] + ev[1] + ev[2] + ev[3]; __syncthreads();
    for (int s = 128; s > 0; s >>= 1) {
        if (tid < s) red[tid] += red[tid + s];
        __syncthreads();
    }
    float scale = egate[slot] / red[0];
    int b = etok[slot];
    #pragma unroll
    for (int q = 0; q < 4; q++)
        atomicAdd(&y[(size_t)b * OO + tid + q * 256], ev[q] * scale);
}

__global__ void zero_y(float* __restrict__ y) {
    int i = blockIdx.x * blockDim.x + threadIdx.x;
    if (i < NB * OO) y[i] = 0.f;
}

// ---------------------------------------------------------------------------
extern "C" void kernel_launch(void* const* d_in, const int* in_sizes, int n_in,
                              void* d_out, int out_size) {
    const float* x   = (const float*)d_in[0];
    const float* cw1 = (const float*)d_in[1];  const float* cb1 = (const float*)d_in[2];
    const float* cw2 = (const float*)d_in[3];  const float* cb2 = (const float*)d_in[4];
    const float* cw3 = (const float*)d_in[5];  const float* cb3 = (const float*)d_in[6];
    const float* cw4 = (const float*)d_in[7];  const float* cb4 = (const float*)d_in[8];
    const float* cw5 = (const float*)d_in[9];  const float* cb5 = (const float*)d_in[10];
    const float* w1  = (const float*)d_in[11]; const float* b1  = (const float*)d_in[12];
    const float* w2  = (const float*)d_in[13]; const float* b2  = (const float*)d_in[14];
    const float* wg  = (const float*)d_in[15];
    float* out = (float*)d_out;

    float *a1, *a2, *a3, *a4, *feats, *logits, *egate, *hbuf, *obuf;
    int *ecnt, *etok;
    cudaGetSymbolAddress((void**)&a1, g_a1);
    cudaGetSymbolAddress((void**)&a2, g_a2);
    cudaGetSymbolAddress((void**)&a3, g_a3);
    cudaGetSymbolAddress((void**)&a4, g_a4);
    cudaGetSymbolAddress((void**)&feats, g_feats);
    cudaGetSymbolAddress((void**)&logits, g_logits);
    cudaGetSymbolAddress((void**)&ecnt, g_ecnt);
    cudaGetSymbolAddress((void**)&etok, g_etok);
    cudaGetSymbolAddress((void**)&egate, g_egate);
    cudaGetSymbolAddress((void**)&hbuf, g_h);
    cudaGetSymbolAddress((void**)&obuf, g_o);

    float* aux_ptr = (out_size > NB * OO) ? (out + NB * OO) : nullptr;

    zero_y<<<(NB * OO + 255) / 256, 256>>>(out);

    conv1_pool<<<dim3(256, 16, 4), 256>>>(x, cw1, cb1, a1);

    // <CI, H, IMG, CG, CO_T, LGW>   COB = CG*CO_T,  NT = IMG*(H/4)^2*CG = 128
    conv_pool2<128, 32, 1, 2, 4, 5><<<dim3(256, 32), 128>>>(a1, cw2, cb2, a2, 256);
    conv_pool2<256, 16, 2, 4, 4, 4><<<dim3(128, 16), 128>>>(a2, cw3, cb3, a3, 256);
    conv_pool2<256,  8, 8, 4, 4, 3><<<dim3( 32, 32), 128>>>(a3, cw4, cb4, a4, 512);
    conv_pool2<512,  4,32, 4, 4, 2><<<dim3(  8, 32), 128>>>(a4, cw5, cb5, feats, 512);

    gate_logits<<<256, 128>>>(feats, wg, logits);
    gate_topk<<<1, 256>>>(logits, ecnt, etok, egate, aux_ptr);

    moe_fc1<<<dim3(16, 8, 32), 128>>>(feats, w1, b1, ecnt, etok, hbuf);
    moe_fc2<<<dim3(16, 2, 32), 128>>>(hbuf, w2, b2, ecnt, obuf);
    moe_combine<<<dim3(16 * 256), 256>>>(obuf, ecnt, egate, etok, out);
}

// round 9
// speedup vs baseline: 1.1165x; 1.0024x over previous
#include <cuda_runtime.h>
#include <cuda_bf16.h>
#include <math.h>

// ---------------------------------------------------------------------------
// ToyMoE round 5: FFMA2-dense conv stack. Each thread: 2x2 pooled block
// (4x4 pre-pool) x CO_T=4 channels -> 288 FFMA2 per ci per thread vs
// 54 LDS.64. ci chunked by 2 (halves barriers). MoE path unchanged.
// ---------------------------------------------------------------------------

#define NB   256
#define DD   2048
#define HID  4096
#define OO   1024
#define EE   16

typedef unsigned long long u64;

__device__ __forceinline__ u64 pack2(float lo, float hi) {
    u64 r; asm("mov.b64 %0, {%1, %2};" : "=l"(r) : "f"(lo), "f"(hi)); return r;
}
__device__ __forceinline__ void unpack2(u64 v, float& lo, float& hi) {
    asm("mov.b64 {%0, %1}, %2;" : "=f"(lo), "=f"(hi) : "l"(v));
}
__device__ __forceinline__ u64 ffma2(u64 a, u64 b, u64 c) {
    u64 d; asm("fma.rn.f32x2 %0, %1, %2, %3;" : "=l"(d) : "l"(a), "l"(b), "l"(c));
    return d;
}

// -------------------- scratch (device globals; no allocs) ------------------
__device__ float g_a1[256 * 128 * 32 * 32];
__device__ float g_a2[256 * 256 * 16 * 16];
__device__ float g_a3[256 * 256 * 8 * 8];
__device__ float g_a4[256 * 512 * 4 * 4];
__device__ float g_feats[256 * 2048];
__device__ float g_logits[256 * 16];
__device__ int   g_ecnt[16];
__device__ int   g_etok[16 * 256];
__device__ float g_egate[16 * 256];
__device__ float g_h[16 * 256 * 4096];
__device__ float g_o[16 * 256 * 1024];

// ---------------------------------------------------------------------------
// Layer 1: CI=3, CO=128, 64x64 -> pooled 32x32. grid (256, 16, 4), 256 thr.
// ---------------------------------------------------------------------------
__global__ void conv1_pool(const float* __restrict__ in,
                           const float* __restrict__ wgt,
                           const float* __restrict__ bias,
                           float* __restrict__ out) {
    const int H = 64, W = 64;
    __shared__ float s_in[3][34][34];
    __shared__ float s_w[8 * 27];

    const int n   = blockIdx.x;
    const int cb0 = blockIdx.y * 8;
    const int tile = blockIdx.z;
    const int ty = (tile / 2) * 16, tx = (tile % 2) * 16;
    const int tid = threadIdx.x;
    const int lph = tid / 16, lpw = tid % 16;

    const int r0 = 2 * ty - 1, c0 = 2 * tx - 1;
    for (int i = tid; i < 3 * 34 * 34; i += 256) {
        int ci = i / (34 * 34);
        int rr = (i / 34) % 34, cc = i % 34;
        int r = r0 + rr, c = c0 + cc;
        float v = 0.f;
        if (r >= 0 && r < H && c >= 0 && c < W)
            v = in[((n * 3 + ci) * H + r) * W + c];
        s_in[ci][rr][cc] = v;
    }
    for (int i = tid; i < 8 * 27; i += 256) s_w[i] = wgt[cb0 * 27 + i];
    __syncthreads();

    float acc[8][4];
    #pragma unroll
    for (int t = 0; t < 8; t++) { acc[t][0]=acc[t][1]=acc[t][2]=acc[t][3]=0.f; }

    #pragma unroll
    for (int ci = 0; ci < 3; ci++) {
        float win[16];
        #pragma unroll
        for (int r = 0; r < 4; r++)
            #pragma unroll
            for (int c = 0; c < 4; c++)
                win[r * 4 + c] = s_in[ci][2 * lph + r][2 * lpw + c];
        #pragma unroll
        for (int t = 0; t < 8; t++) {
            const float* wp = &s_w[t * 27 + ci * 9];
            float w0=wp[0],w1=wp[1],w2=wp[2],w3=wp[3],w4=wp[4],w5=wp[5],w6=wp[6],w7=wp[7],w8=wp[8];
            #pragma unroll
            for (int dy = 0; dy < 2; dy++)
                #pragma unroll
                for (int dx = 0; dx < 2; dx++) {
                    float s = win[(dy+0)*4 + dx+0]*w0 + win[(dy+0)*4 + dx+1]*w1 + win[(dy+0)*4 + dx+2]*w2
                            + win[(dy+1)*4 + dx+0]*w3 + win[(dy+1)*4 + dx+1]*w4 + win[(dy+1)*4 + dx+2]*w5
                            + win[(dy+2)*4 + dx+0]*w6 + win[(dy+2)*4 + dx+1]*w7 + win[(dy+2)*4 + dx+2]*w8;
                    acc[t][dy * 2 + dx] += s;
                }
        }
    }
    const int ph = ty + lph, pw = tx + lpw;
    #pragma unroll
    for (int t = 0; t < 8; t++) {
        int co = cb0 + t;
        float b = bias[co];
        float m = fmaxf(fmaxf(acc[t][0], acc[t][1]), fmaxf(acc[t][2], acc[t][3]));
        out[(((size_t)n * 128 + co) * 32 + ph) * 32 + pw] = fmaxf(m + b, 0.f);
    }
}

// ---------------------------------------------------------------------------
// Layers 2..5: FFMA2-dense fused conv3x3+bias+relu+maxpool2.
// Thread tile: 2x2 pooled (4x4 pre-pool) x CO_T channels.
// CTA: IMG images x NBLK pooled-blocks x CG channel groups = 128 threads.
// ci chunked by 2: stage 2 channels -> bar -> compute both -> bar.
// Accumulation order per output identical to previous rounds.
// ---------------------------------------------------------------------------
template <int CI, int H, int IMG, int CG, int CO_T, int LGW>
__global__ void __launch_bounds__(128)
conv_pool2(const float* __restrict__ in,
           const float* __restrict__ wgt,
           const float* __restrict__ bias,
           float* __restrict__ out, int CO) {
    constexpr int W = H, HW = H * W, LG_HW = 2 * LGW;
    constexpr int P = H / 2, PB = P / 2, NBLK = PB * PB;
    constexpr int SP = H + 2, HPAD = H + 2, PLANE = HPAD * SP;
    constexpr int NT = IMG * NBLK * CG;
    constexpr int COB = CG * CO_T;
    static_assert(NT == 128, "128 threads expected");

    __shared__ float s_in[2][IMG * PLANE];
    __shared__ u64  s_w2[2][COB * 9];

    const int n0  = blockIdx.x * IMG;
    const int cb0 = blockIdx.y * COB;
    const int tid = threadIdx.x;
    const int b   = tid % NBLK;
    const int j   = (tid / NBLK) % IMG;
    const int cg  = tid / (NBLK * IMG);
    const int bx  = b % PB, by = b / PB;

    // zero whole input buffers once (halo stays zero; interior overwritten)
    for (int i = tid; i < IMG * PLANE; i += NT) { s_in[0][i] = 0.f; s_in[1][i] = 0.f; }
    __syncthreads();

    u64 acc[CO_T][4][2];
    #pragma unroll
    for (int t = 0; t < CO_T; t++)
        #pragma unroll
        for (int dy = 0; dy < 4; dy++) { acc[t][dy][0] = 0ull; acc[t][dy][1] = 0ull; }

    for (int cc0 = 0; cc0 < CI; cc0 += 2) {
        // ---- stage 2 channels (interior + packed weights) ----
        #pragma unroll
        for (int c = 0; c < 2; c++) {
            const int ci = cc0 + c;
            const float* ip = in + (size_t)n0 * CI * HW + (size_t)ci * HW;
            for (int i = tid; i < IMG * HW; i += NT) {
                int jj = i >> LG_HW;
                int rest = i & (HW - 1);
                int r = rest >> LGW, cx = rest & (W - 1);
                s_in[c][jj * PLANE + (r + 1) * SP + cx + 1] =
                    ip[(size_t)jj * CI * HW + rest];
            }
            for (int i = tid; i < COB * 9; i += NT) {
                float wv = wgt[(size_t)(cb0 + i / 9) * CI * 9 + ci * 9 + (i % 9)];
                s_w2[c][i] = pack2(wv, wv);
            }
        }
        __syncthreads();

        // ---- compute both channels ----
        #pragma unroll
        for (int c = 0; c < 2; c++) {
            u64 w[CO_T][9];
            #pragma unroll
            for (int t = 0; t < CO_T; t++)
                #pragma unroll
                for (int k = 0; k < 9; k++)
                    w[t][k] = s_w2[c][(cg * CO_T + t) * 9 + k];

            const float* base = &s_in[c][j * PLANE + (4 * by) * SP + 4 * bx];
            #pragma unroll
            for (int wr = 0; wr < 6; wr++) {
                // 6 consecutive floats as 3 aligned LDS.64 (row*SP+4bx is even)
                const u64* rp = (const u64*)(base + wr * SP);
                u64 wp[5];
                wp[0] = rp[0]; wp[2] = rp[1]; wp[4] = rp[2];
                float f0, f1, f2, f3, f4, f5;
                unpack2(wp[0], f0, f1); unpack2(wp[2], f2, f3); unpack2(wp[4], f4, f5);
                wp[1] = pack2(f1, f2); wp[3] = pack2(f3, f4);

                #pragma unroll
                for (int dy = 0; dy < 4; dy++) {
                    if (wr - dy < 0 || wr - dy > 2) continue;
                    const int kr = wr - dy;
                    #pragma unroll
                    for (int t = 0; t < CO_T; t++)
                        #pragma unroll
                        for (int cc = 0; cc < 3; cc++) {
                            acc[t][dy][0] = ffma2(wp[cc],     w[t][kr * 3 + cc], acc[t][dy][0]);
                            acc[t][dy][1] = ffma2(wp[2 + cc], w[t][kr * 3 + cc], acc[t][dy][1]);
                        }
                }
            }
        }
        __syncthreads();
    }

    // ---- epilogue: maxpool 2x2 + bias + relu ----
    #pragma unroll
    for (int t = 0; t < CO_T; t++) {
        const int co = cb0 + cg * CO_T + t;
        const float bv = bias[co];
        float v[4][4];
        #pragma unroll
        for (int dy = 0; dy < 4; dy++) {
            unpack2(acc[t][dy][0], v[dy][0], v[dy][1]);
            unpack2(acc[t][dy][1], v[dy][2], v[dy][3]);
        }
        #pragma unroll
        for (int py = 0; py < 2; py++)
            #pragma unroll
            for (int px = 0; px < 2; px++) {
                float m = fmaxf(fmaxf(v[2*py][2*px], v[2*py][2*px+1]),
                                fmaxf(v[2*py+1][2*px], v[2*py+1][2*px+1]));
                out[(((size_t)(n0 + j) * CO + co) * P + (2 * by + py)) * P + (2 * bx + px)]
                    = fmaxf(m + bv, 0.f);
            }
    }
}

// ---------------------------------------------------------------------------
// Gating: logits = feats @ w_gate   (grid 256, 128 threads)
// ---------------------------------------------------------------------------
__global__ void gate_logits(const float* __restrict__ feats,
                            const float* __restrict__ wg,
                            float* __restrict__ logits) {
    const int b = blockIdx.x, tid = threadIdx.x;
    float acc[16];
    #pragma unroll
    for (int e = 0; e < 16; e++) acc[e] = 0.f;
    for (int d = tid; d < DD; d += 128) {
        float f = feats[(size_t)b * DD + d];
        const float* wr = wg + (size_t)d * 16;
        #pragma unroll
        for (int e = 0; e < 16; e++) acc[e] += f * wr[e];
    }
    __shared__ float sacc[128][16];
    #pragma unroll
    for (int e = 0; e < 16; e++) sacc[tid][e] = acc[e];
    __syncthreads();
    if (tid < 16) {
        float s = 0.f;
        for (int i = 0; i < 128; i++) s += sacc[i][tid];
        logits[b * 16 + tid] = s;
    }
}

// ---------------------------------------------------------------------------
// Top-2 gating + expert grouping + aux loss. Single block, 256 threads.
// ---------------------------------------------------------------------------
__global__ void gate_topk(const float* __restrict__ logits,
                          int* __restrict__ ecnt, int* __restrict__ etok,
                          float* __restrict__ egate, float* __restrict__ out_aux) {
    __shared__ int   s_e1[256], s_e2[256];
    __shared__ float s_g1[256], s_g2[256];
    __shared__ float s_imp[16], s_load[16];
    const int tid = threadIdx.x;

    const float* lr = logits + tid * 16;
    float v1 = -1e30f; int i1 = 0;
    #pragma unroll
    for (int e = 0; e < 16; e++) { float v = lr[e]; if (v > v1) { v1 = v; i1 = e; } }
    float v2 = -1e30f; int i2 = 0;
    #pragma unroll
    for (int e = 0; e < 16; e++) { if (e == i1) continue; float v = lr[e]; if (v > v2) { v2 = v; i2 = e; } }
    float ex = expf(v2 - v1);
    float inv = 1.f / (1.f + ex);
    s_e1[tid] = i1; s_e2[tid] = i2;
    s_g1[tid] = inv; s_g2[tid] = ex * inv;
    __syncthreads();

    if (tid < 16) {
        int e = tid, cnt = 0; float imp = 0.f;
        for (int b = 0; b < 256; b++) {
            if (s_e1[b] == e && s_g1[b] > 0.f) {
                etok[e * 256 + cnt] = b; egate[e * 256 + cnt] = s_g1[b];
                cnt++; imp += s_g1[b];
            } else if (s_e2[b] == e && s_g2[b] > 0.f) {
                etok[e * 256 + cnt] = b; egate[e * 256 + cnt] = s_g2[b];
                cnt++; imp += s_g2[b];
            }
        }
        ecnt[e] = cnt; s_imp[e] = imp; s_load[e] = (float)cnt;
    }
    __syncthreads();
    if (tid == 0 && out_aux != nullptr) {
        float mi = 0.f, ml = 0.f;
        for (int e = 0; e < 16; e++) { mi += s_imp[e]; ml += s_load[e]; }
        mi /= 16.f; ml /= 16.f;
        float vi = 0.f, vl = 0.f;
        for (int e = 0; e < 16; e++) {
            float a = s_imp[e] - mi; vi += a * a;
            float b = s_load[e] - ml; vl += b * b;
        }
        vi /= 16.f; vl /= 16.f;
        *out_aux = 0.01f * (vi / (mi * mi + 1e-10f) + vl / (ml * ml + 1e-10f));
    }
}

// ---------------------------------------------------------------------------
// fc1: h = relu(feats @ w1[e] + b1[e])  grid (16, 8, 32), 128 threads
// ---------------------------------------------------------------------------
__global__ void moe_fc1(const float* __restrict__ feats,
                        const float* __restrict__ w1,
                        const float* __restrict__ b1,
                        const int* __restrict__ ecnt,
                        const int* __restrict__ etok,
                        float* __restrict__ hbuf) {
    constexpr int TB = 8, HT = 4;
    const int e = blockIdx.x;
    const int cnt = ecnt[e];
    const int t0 = blockIdx.z * TB;
    if (t0 >= cnt) return;
    const int tid = threadIdx.x;
    const int hid0 = blockIdx.y * 512 + tid;

    __shared__ float fch[TB][64];
    __shared__ int stok[TB];
    if (tid < TB) {
        int tt = t0 + tid; if (tt >= cnt) tt = cnt - 1;
        stok[tid] = etok[e * 256 + tt];
    }
    __syncthreads();

    float acc[TB][HT];
    #pragma unroll
    for (int j = 0; j < TB; j++)
        #pragma unroll
        for (int q = 0; q < HT; q++) acc[j][q] = 0.f;

    const float* w1e = w1 + (size_t)e * DD * HID;
    for (int dc = 0; dc < DD; dc += 64) {
        for (int i = tid; i < TB * 64; i += 128) {
            int j = i / 64, dd = i % 64;
            fch[j][dd] = feats[(size_t)stok[j] * DD + dc + dd];
        }
        __syncthreads();
        for (int dd = 0; dd < 64; dd++) {
            float wv[HT];
            const float* wrow = w1e + (size_t)(dc + dd) * HID + hid0;
            #pragma unroll
            for (int q = 0; q < HT; q++) wv[q] = wrow[q * 128];
            #pragma unroll
            for (int j = 0; j < TB; j++) {
                float f = fch[j][dd];
                #pragma unroll
                for (int q = 0; q < HT; q++) acc[j][q] += f * wv[q];
            }
        }
        __syncthreads();
    }
    float bias[HT];
    #pragma unroll
    for (int q = 0; q < HT; q++) bias[q] = b1[e * HID + hid0 + q * 128];
    for (int j = 0; j < TB; j++) {
        if (t0 + j >= cnt) break;
        size_t slot = (size_t)(e * 256 + t0 + j);
        #pragma unroll
        for (int q = 0; q < HT; q++)
            hbuf[slot * HID + hid0 + q * 128] = fmaxf(acc[j][q] + bias[q], 0.f);
    }
}

// ---------------------------------------------------------------------------
// fc2: o = h @ w2[e] + b2[e]     grid (16, 2, 32), 128 threads
// ---------------------------------------------------------------------------
__global__ void moe_fc2(const float* __restrict__ hbuf,
                        const float* __restrict__ w2,
                        const float* __restrict__ b2,
                        const int* __restrict__ ecnt,
                        float* __restrict__ obuf) {
    constexpr int TB = 8, HT = 4;
    const int e = blockIdx.x;
    const int cnt = ecnt[e];
    const int t0 = blockIdx.z * TB;
    if (t0 >= cnt) return;
    const int tid = threadIdx.x;
    const int o0 = blockIdx.y * 512 + tid;

    __shared__ float hch[TB][64];

    float acc[TB][HT];
    #pragma unroll
    for (int j = 0; j < TB; j++)
        #pragma unroll
        for (int q = 0; q < HT; q++) acc[j][q] = 0.f;

    const float* w2e = w2 + (size_t)e * HID * OO;
    for (int hc = 0; hc < HID; hc += 64) {
        for (int i = tid; i < TB * 64; i += 128) {
            int j = i / 64, dd = i % 64;
            int tt = t0 + j; if (tt >= cnt) tt = cnt - 1;
            hch[j][dd] = hbuf[(size_t)(e * 256 + tt) * HID + hc + dd];
        }
        __syncthreads();
        for (int dd = 0; dd < 64; dd++) {
            float wv[HT];
            const float* wrow = w2e + (size_t)(hc + dd) * OO + o0;
            #pragma unroll
            for (int q = 0; q < HT; q++) wv[q] = wrow[q * 128];
            #pragma unroll
            for (int j = 0; j < TB; j++) {
                float h = hch[j][dd];
                #pragma unroll
                for (int q = 0; q < HT; q++) acc[j][q] += h * wv[q];
            }
        }
        __syncthreads();
    }
    float bias[HT];
    #pragma unroll
    for (int q = 0; q < HT; q++) bias[q] = b2[e * OO + o0 + q * 128];
    for (int j = 0; j < TB; j++) {
        if (t0 + j >= cnt) break;
        size_t slot = (size_t)(e * 256 + t0 + j);
        #pragma unroll
        for (int q = 0; q < HT; q++)
            obuf[slot * OO + o0 + q * 128] = acc[j][q] + bias[q];
    }
}

// ---------------------------------------------------------------------------
// softmax over o row + gate-weighted accumulate into y. grid 4096, 256 threads
// ---------------------------------------------------------------------------
__global__ void moe_combine(const float* __restrict__ obuf,
                            const int* __restrict__ ecnt,
                            const float* __restrict__ egate,
                            const int* __restrict__ etok,
                            float* __restrict__ y) {
    const int e = blockIdx.x >> 8;
    const int pos = blockIdx.x & 255;
    if (pos >= ecnt[e]) return;
    const int slot = e * 256 + pos;
    const int tid = threadIdx.x;
    const float* orow = obuf + (size_t)slot * OO;

    float v[4];
    #pragma unroll
    for (int q = 0; q < 4; q++) v[q] = orow[tid + q * 256];

    __shared__ float red[256];
    float m4 = fmaxf(fmaxf(v[0], v[1]), fmaxf(v[2], v[3]));
    red[tid] = m4; __syncthreads();
    for (int s = 128; s > 0; s >>= 1) {
        if (tid < s) red[tid] = fmaxf(red[tid], red[tid + s]);
        __syncthreads();
    }
    float m = red[0]; __syncthreads();

    float ev[4];
    #pragma unroll
    for (int q = 0; q < 4; q++) ev[q] = expf(v[q] - m);
    red[tid] = ev[0] + ev[1] + ev[2] + ev[3]; __syncthreads();
    for (int s = 128; s > 0; s >>= 1) {
        if (tid < s) red[tid] += red[tid + s];
        __syncthreads();
    }
    float scale = egate[slot] / red[0];
    int b = etok[slot];
    #pragma unroll
    for (int q = 0; q < 4; q++)
        atomicAdd(&y[(size_t)b * OO + tid + q * 256], ev[q] * scale);
}

__global__ void zero_y(float* __restrict__ y) {
    int i = blockIdx.x * blockDim.x + threadIdx.x;
    if (i < NB * OO) y[i] = 0.f;
}

// ---------------------------------------------------------------------------
extern "C" void kernel_launch(void* const* d_in, const int* in_sizes, int n_in,
                              void* d_out, int out_size) {
    const float* x   = (const float*)d_in[0];
    const float* cw1 = (const float*)d_in[1];  const float* cb1 = (const float*)d_in[2];
    const float* cw2 = (const float*)d_in[3];  const float* cb2 = (const float*)d_in[4];
    const float* cw3 = (const float*)d_in[5];  const float* cb3 = (const float*)d_in[6];
    const float* cw4 = (const float*)d_in[7];  const float* cb4 = (const float*)d_in[8];
    const float* cw5 = (const float*)d_in[9];  const float* cb5 = (const float*)d_in[10];
    const float* w1  = (const float*)d_in[11]; const float* b1  = (const float*)d_in[12];
    const float* w2  = (const float*)d_in[13]; const float* b2  = (const float*)d_in[14];
    const float* wg  = (const float*)d_in[15];
    float* out = (float*)d_out;

    float *a1, *a2, *a3, *a4, *feats, *logits, *egate, *hbuf, *obuf;
    int *ecnt, *etok;
    cudaGetSymbolAddress((void**)&a1, g_a1);
    cudaGetSymbolAddress((void**)&a2, g_a2);
    cudaGetSymbolAddress((void**)&a3, g_a3);
    cudaGetSymbolAddress((void**)&a4, g_a4);
    cudaGetSymbolAddress((void**)&feats, g_feats);
    cudaGetSymbolAddress((void**)&logits, g_logits);
    cudaGetSymbolAddress((void**)&ecnt, g_ecnt);
    cudaGetSymbolAddress((void**)&etok, g_etok);
    cudaGetSymbolAddress((void**)&egate, g_egate);
    cudaGetSymbolAddress((void**)&hbuf, g_h);
    cudaGetSymbolAddress((void**)&obuf, g_o);

    float* aux_ptr = (out_size > NB * OO) ? (out + NB * OO) : nullptr;

    zero_y<<<(NB * OO + 255) / 256, 256>>>(out);

    conv1_pool<<<dim3(256, 16, 4), 256>>>(x, cw1, cb1, a1);

    // <CI, H, IMG, CG, CO_T, LGW>   COB = CG*CO_T,  NT = IMG*(H/4)^2*CG = 128
    conv_pool2<128, 32, 1, 2, 4, 5><<<dim3(256, 32), 128>>>(a1, cw2, cb2, a2, 256);
    conv_pool2<256, 16, 2, 4, 4, 4><<<dim3(128, 16), 128>>>(a2, cw3, cb3, a3, 256);
    conv_pool2<256,  8, 8, 4, 4, 3><<<dim3( 32, 32), 128>>>(a3, cw4, cb4, a4, 512);
    conv_pool2<512,  4,32, 4, 4, 2><<<dim3(  8, 32), 128>>>(a4, cw5, cb5, feats, 512);

    gate_logits<<<256, 128>>>(feats, wg, logits);
    gate_topk<<<1, 256>>>(logits, ecnt, etok, egate, aux_ptr);

    moe_fc1<<<dim3(16, 8, 32), 128>>>(feats, w1, b1, ecnt, etok, hbuf);
    moe_fc2<<<dim3(16, 2, 32), 128>>>(hbuf, w2, b2, ecnt, obuf);
    moe_combine<<<dim3(16 * 256), 256>>>(obuf, ecnt, egate, etok, out);
}

// round 12
// speedup vs baseline: 2.0341x; 1.8218x over previous
#include <cuda_runtime.h>
#include <cuda_bf16.h>
#include <math.h>
#include <stdint.h>

#define NB 256
#define DD 2048
#define HID 4096
#define OO 1024

__device__ __forceinline__ uint32_t smem_u32(const void* p) {
    uint32_t a;
    asm("{ .reg .u64 t; cvta.to.shared.u64 t, %1; cvt.u32.u64 %0, t; }" : "=r"(a) : "l"(p));
    return a;
}
#define LDSM4(r, a) \
    asm volatile("ldmatrix.sync.aligned.m8n8.x4.shared.b16 {%0,%1,%2,%3}, [%4];" \
        : "=r"((r)[0]), "=r"((r)[1]), "=r"((r)[2]), "=r"((r)[3]) : "r"(a))
#define MMA(c, a, b0, b1) \
    asm volatile("mma.sync.aligned.m16n8k16.row.col.f32.bf16.bf16.f32 " \
        "{%0,%1,%2,%3},{%4,%5,%6,%7},{%8,%9},{%0,%1,%2,%3};" \
        : "+f"((c)[0]), "+f"((c)[1]), "+f"((c)[2]), "+f"((c)[3]) \
        : "r"((a)[0]), "r"((a)[1]), "r"((a)[2]), "r"((a)[3]), "r"(b0), "r"(b1))

// ---- scratch (zero-init device globals; halo rows never written => stay 0) ----
// act rows: [gp][3*CI bf16] = [a_hi(CI) | a_lo(CI) | a_hi(CI)], LEAD=128 rows.
__device__ uint16_t g_act2[(size_t)296320 * 384];   // 128+256*1156+256 rows
__device__ uint16_t g_act3[(size_t)83328 * 768];    // 128+256*324+256
__device__ uint16_t g_act4[(size_t)25984 * 768];    // 128+256*100+256
__device__ uint16_t g_act5[(size_t)9600 * 1536];    // 128+256*36+256
// weights rows: [tap][co][3*CI] = [w_hi | w_hi | w_lo]
__device__ uint16_t g_wt2[(size_t)9 * 256 * 384];
__device__ uint16_t g_wt3[(size_t)9 * 256 * 768];
__device__ uint16_t g_wt4[(size_t)9 * 512 * 768];
__device__ uint16_t g_wt5[(size_t)9 * 512 * 1536];
__device__ float g_prepool[(size_t)256 * 32 * 32 * 256];  // NHWC, reused
__device__ float g_feats[256 * 2048];
__device__ float g_logits[256 * 16];
__device__ int   g_ecnt[16];
__device__ int   g_etok[16 * 256];
__device__ float g_egate[16 * 256];
__device__ float g_h[(size_t)16 * 256 * 4096];
__device__ float g_o[(size_t)16 * 256 * 1024];

__device__ __forceinline__ void split_bf16(float v, uint16_t& hb, uint16_t& lb) {
    __nv_bfloat16 h = __float2bfloat16(v);
    __nv_bfloat16 l = __float2bfloat16(v - __bfloat162float(h));
    hb = __bfloat16_as_ushort(h); lb = __bfloat16_as_ushort(l);
}

// w[CO][CI][3][3] -> wt[tap][co][3CI]
__global__ void prep_w(const float* __restrict__ w, uint16_t* __restrict__ wt, int CI, int CO) {
    int idx = blockIdx.x * 256 + threadIdx.x;
    if (idx >= CO * CI) return;
    int co = idx / CI, ci = idx % CI, RL = 3 * CI;
    #pragma unroll
    for (int k = 0; k < 9; k++) {
        uint16_t hb, lb; split_bf16(w[((size_t)co * CI + ci) * 9 + k], hb, lb);
        size_t base = ((size_t)k * CO + co) * RL;
        wt[base + ci] = hb; wt[base + CI + ci] = hb; wt[base + 2 * CI + ci] = lb;
    }
}

// conv1 fp32 SIMT -> act2 tripled rows. grid (256,16,4), 256 thr
__global__ void conv1_pool(const float* __restrict__ in, const float* __restrict__ wgt,
                           const float* __restrict__ bias, uint16_t* __restrict__ act2) {
    const int H = 64, W = 64;
    __shared__ float s_in[3][34][34];
    __shared__ float s_w[8 * 27];
    const int n = blockIdx.x, cb0 = blockIdx.y * 8, tile = blockIdx.z;
    const int ty = (tile / 2) * 16, tx = (tile % 2) * 16;
    const int tid = threadIdx.x, lph = tid / 16, lpw = tid % 16;
    const int r0 = 2 * ty - 1, c0 = 2 * tx - 1;
    for (int i = tid; i < 3 * 34 * 34; i += 256) {
        int ci = i / 1156, rr = (i / 34) % 34, cc = i % 34;
        int r = r0 + rr, c = c0 + cc;
        float v = 0.f;
        if (r >= 0 && r < H && c >= 0 && c < W) v = in[((n * 3 + ci) * H + r) * W + c];
        s_in[ci][rr][cc] = v;
    }
    for (int i = tid; i < 8 * 27; i += 256) s_w[i] = wgt[cb0 * 27 + i];
    __syncthreads();
    float acc[8][4];
    #pragma unroll
    for (int t = 0; t < 8; t++) acc[t][0]=acc[t][1]=acc[t][2]=acc[t][3]=0.f;
    #pragma unroll
    for (int ci = 0; ci < 3; ci++) {
        float win[16];
        #pragma unroll
        for (int r = 0; r < 4; r++)
            #pragma unroll
            for (int c = 0; c < 4; c++) win[r*4+c] = s_in[ci][2*lph+r][2*lpw+c];
        #pragma unroll
        for (int t = 0; t < 8; t++) {
            const float* wp = &s_w[t * 27 + ci * 9];
            #pragma unroll
            for (int dy = 0; dy < 2; dy++)
                #pragma unroll
                for (int dx = 0; dx < 2; dx++) {
                    float s = win[dy*4+dx]*wp[0] + win[dy*4+dx+1]*wp[1] + win[dy*4+dx+2]*wp[2]
                            + win[(dy+1)*4+dx]*wp[3] + win[(dy+1)*4+dx+1]*wp[4] + win[(dy+1)*4+dx+2]*wp[5]
                            + win[(dy+2)*4+dx]*wp[6] + win[(dy+2)*4+dx+1]*wp[7] + win[(dy+2)*4+dx+2]*wp[8];
                    acc[t][dy*2+dx] += s;
                }
        }
    }
    const int ph = ty + lph, pw = tx + lpw;
    const size_t gp = 128 + (size_t)n * 1156 + (ph + 1) * 34 + (pw + 1);
    #pragma unroll
    for (int t = 0; t < 8; t++) {
        int co = cb0 + t;
        float m = fmaxf(fmaxf(acc[t][0], acc[t][1]), fmaxf(acc[t][2], acc[t][3]));
        float v = fmaxf(m + bias[co], 0.f);
        uint16_t hb, lb; split_bf16(v, hb, lb);
        size_t b = gp * 384;
        act2[b + co] = hb; act2[b + 128 + co] = lb; act2[b + 256 + co] = hb;
    }
}

// ------------- HMMA implicit-GEMM conv: 128 px x 128 co per CTA -------------
template <int CI, int H, int W, int CO>
__global__ void __launch_bounds__(256, 2)
conv_mma(const uint16_t* __restrict__ act, const uint16_t* __restrict__ wt,
         const float* __restrict__ bias, float* __restrict__ prepool) {
    constexpr int Wp = W + 2, PPI = (H + 2) * Wp;
    constexpr int RL = 3 * CI, KC3 = RL / 16, S = KC3 * 9;
    constexpr int AROWS = 130 + 2 * Wp;
    __shared__ uint8_t abuf[AROWS * 48];
    __shared__ uint8_t bbuf[2][128 * 48];

    const int tid = threadIdx.x, lane = tid & 31, warp = tid >> 5;
    const int wm = warp >> 1, wn = warp & 1;
    const int gp0 = blockIdx.x * 128, cb0 = blockIdx.y * 128;
    const int lm = lane >> 3, lr = lane & 7;

    float c[2][8][4];
    #pragma unroll
    for (int i = 0; i < 2; i++)
        #pragma unroll
        for (int j = 0; j < 8; j++)
            #pragma unroll
            for (int q = 0; q < 4; q++) c[i][j][q] = 0.f;

    // ldmatrix lane addressing
    const int arb = (Wp + 1) + wm * 32 + (lm & 1) * 8 + lr;   // A row for this lane
    const uint32_t abyte = (uint32_t)(lm >> 1) * 16;
    const uint32_t a_sm = smem_u32(abuf);
    const uint32_t bcol = (uint32_t)(wn * 64 + (lm >> 1) * 8 + lr) * 48 + (lm & 1) * 16;
    const uint32_t b_sm0 = smem_u32(bbuf[0]) + bcol;
    const uint32_t b_sm1 = smem_u32(bbuf[1]) + bcol;

    // B prefetch: row = tid>>1, 16B half = tid&1
    const int brow = tid >> 1, bhalf = tid & 1;
    uint4 breg = *(const uint4*)(wt + ((size_t)(cb0 + brow)) * RL + bhalf * 8);

    int tap = 0, kc = 0;
    for (int s = 0; s < S; s++) {
        if (tap == 0) {
            __syncthreads();
            if (tid < AROWS) {
                const uint4* src = (const uint4*)(act +
                    ((size_t)(gp0 + 128 - (Wp + 1) + tid)) * RL + kc * 16);
                uint4 v0 = src[0], v1 = src[1];
                uint4* dst = (uint4*)(abuf + tid * 48);
                dst[0] = v0; dst[1] = v1;
            }
        }
        *(uint4*)(bbuf[s & 1] + brow * 48 + bhalf * 16) = breg;
        __syncthreads();
        if (s + 1 < S) {
            int t2 = tap + 1, k2 = kc;
            if (t2 == 9) { t2 = 0; k2 = kc + 1; }
            breg = *(const uint4*)(wt +
                ((size_t)t2 * CO + cb0 + brow) * RL + k2 * 16 + bhalf * 8);
        }
        const int dtap = (tap / 3 - 1) * Wp + (tap % 3 - 1);
        const uint32_t aaddr = a_sm + (uint32_t)(arb + dtap) * 48 + abyte;
        uint32_t a0[4], a1[4];
        LDSM4(a0, aaddr);
        LDSM4(a1, aaddr + 16 * 48);
        const uint32_t bb = (s & 1) ? b_sm1 : b_sm0;
        #pragma unroll
        for (int ng = 0; ng < 4; ng++) {
            uint32_t b[4];
            LDSM4(b, bb + ng * (16 * 48));
            MMA(c[0][ng * 2],     a0, b[0], b[1]);
            MMA(c[0][ng * 2 + 1], a0, b[2], b[3]);
            MMA(c[1][ng * 2],     a1, b[0], b[1]);
            MMA(c[1][ng * 2 + 1], a1, b[2], b[3]);
        }
        if (++tap == 9) { tap = 0; kc++; }
    }

    // epilogue: bias + relu, interior pixels only, NHWC prepool
    const int r1 = lane >> 2, colp = (lane & 3) * 2;
    #pragma unroll
    for (int mt = 0; mt < 2; mt++) {
        #pragma unroll
        for (int half = 0; half < 2; half++) {
            const int gp = gp0 + wm * 32 + mt * 16 + r1 + half * 8;
            const int img = gp / PPI, within = gp % PPI;
            const int y = within / Wp, x = within % Wp;
            if (y < 1 || y > H || x < 1 || x > W) continue;
            float* base = prepool + ((((size_t)img * H + (y - 1)) * W + (x - 1)) * CO + cb0 + wn * 64);
            #pragma unroll
            for (int nt = 0; nt < 8; nt++) {
                const int co = nt * 8 + colp;
                float2 o;
                o.x = fmaxf(c[mt][nt][half * 2 + 0] + bias[cb0 + wn * 64 + co], 0.f);
                o.y = fmaxf(c[mt][nt][half * 2 + 1] + bias[cb0 + wn * 64 + co + 1], 0.f);
                *(float2*)(base + co) = o;
            }
        }
    }
}

// maxpool 2x2 on relu'd prepool (NHWC) -> next tripled act rows
__global__ void pool_to_act(const float* __restrict__ prepool, uint16_t* __restrict__ actn,
                            int Hin, int CO) {
    const int P = Hin >> 1, RL = 3 * CO;
    int idx = blockIdx.x * 256 + threadIdx.x;
    if (idx >= 256 * P * P * CO) return;
    int c = idx % CO, px = (idx / CO) % P, py = (idx / (CO * P)) % P, n = idx / (CO * P * P);
    const float* base = prepool + (((size_t)n * Hin + 2 * py) * Hin + 2 * px) * CO + c;
    float v = fmaxf(fmaxf(base[0], base[CO]),
                    fmaxf(base[(size_t)Hin * CO], base[(size_t)Hin * CO + CO]));
    int Pp = P + 2;
    size_t gp = 128 + (size_t)n * Pp * Pp + (py + 1) * Pp + (px + 1);
    uint16_t hb, lb; split_bf16(v, hb, lb);
    size_t b = gp * RL;
    actn[b + c] = hb; actn[b + CO + c] = lb; actn[b + 2 * CO + c] = hb;
}

// conv5 pool -> feats fp32, NCHW-flatten (d = c*4 + py*2 + px)
__global__ void pool_to_feats(const float* __restrict__ prepool, float* __restrict__ feats) {
    int idx = blockIdx.x * 256 + threadIdx.x;
    if (idx >= 256 * 4 * 512) return;
    int c = idx % 512, px = (idx / 512) & 1, py = (idx / 1024) & 1, n = idx / 2048;
    const float* base = prepool + (((size_t)n * 4 + 2 * py) * 4 + 2 * px) * 512 + c;
    float v = fmaxf(fmaxf(base[0], base[512]), fmaxf(base[4 * 512], base[4 * 512 + 512]));
    feats[(size_t)n * DD + c * 4 + py * 2 + px] = v;
}

__global__ void gate_logits(const float* __restrict__ feats, const float* __restrict__ wg,
                            float* __restrict__ logits) {
    const int b = blockIdx.x, tid = threadIdx.x;
    float acc[16];
    #pragma unroll
    for (int e = 0; e < 16; e++) acc[e] = 0.f;
    for (int d = tid; d < DD; d += 128) {
        float f = feats[(size_t)b * DD + d];
        const float* wr = wg + (size_t)d * 16;
        #pragma unroll
        for (int e = 0; e < 16; e++) acc[e] += f * wr[e];
    }
    __shared__ float sacc[128][16];
    #pragma unroll
    for (int e = 0; e < 16; e++) sacc[tid][e] = acc[e];
    __syncthreads();
    if (tid < 16) {
        float s = 0.f;
        for (int i = 0; i < 128; i++) s += sacc[i][tid];
        logits[b * 16 + tid] = s;
    }
}

__global__ void gate_topk(const float* __restrict__ logits, int* __restrict__ ecnt,
                          int* __restrict__ etok, float* __restrict__ egate,
                          float* __restrict__ out_aux) {
    __shared__ int s_e1[256], s_e2[256];
    __shared__ float s_g1[256], s_g2[256], s_imp[16], s_load[16];
    const int tid = threadIdx.x;
    const float* lr = logits + tid * 16;
    float v1 = -1e30f; int i1 = 0;
    #pragma unroll
    for (int e = 0; e < 16; e++) { float v = lr[e]; if (v > v1) { v1 = v; i1 = e; } }
    float v2 = -1e30f; int i2 = 0;
    #pragma unroll
    for (int e = 0; e < 16; e++) { if (e == i1) continue; float v = lr[e]; if (v > v2) { v2 = v; i2 = e; } }
    float ex = expf(v2 - v1), inv = 1.f / (1.f + ex);
    s_e1[tid] = i1; s_e2[tid] = i2; s_g1[tid] = inv; s_g2[tid] = ex * inv;
    __syncthreads();
    if (tid < 16) {
        int e = tid, cnt = 0; float imp = 0.f;
        for (int b = 0; b < 256; b++) {
            if (s_e1[b] == e && s_g1[b] > 0.f) {
                etok[e*256+cnt] = b; egate[e*256+cnt] = s_g1[b]; cnt++; imp += s_g1[b];
            } else if (s_e2[b] == e && s_g2[b] > 0.f) {
                etok[e*256+cnt] = b; egate[e*256+cnt] = s_g2[b]; cnt++; imp += s_g2[b];
            }
        }
        ecnt[e] = cnt; s_imp[e] = imp; s_load[e] = (float)cnt;
    }
    __syncthreads();
    if (tid == 0 && out_aux != nullptr) {
        float mi = 0.f, ml = 0.f;
        for (int e = 0; e < 16; e++) { mi += s_imp[e]; ml += s_load[e]; }
        mi /= 16.f; ml /= 16.f;
        float vi = 0.f, vl = 0.f;
        for (int e = 0; e < 16; e++) {
            float a = s_imp[e] - mi; vi += a * a;
            float b = s_load[e] - ml; vl += b * b;
        }
        vi /= 16.f; vl /= 16.f;
        *out_aux = 0.01f * (vi / (mi * mi + 1e-10f) + vl / (ml * ml + 1e-10f));
    }
}

__global__ void moe_fc1(const float* __restrict__ feats, const float* __restrict__ w1,
                        const float* __restrict__ b1, const int* __restrict__ ecnt,
                        const int* __restrict__ etok, float* __restrict__ hbuf) {
    constexpr int TB = 8, HT = 4;
    const int e = blockIdx.x, cnt = ecnt[e], t0 = blockIdx.z * TB;
    if (t0 >= cnt) return;
    const int tid = threadIdx.x, hid0 = blockIdx.y * 512 + tid;
    __shared__ float fch[TB][64];
    __shared__ int stok[TB];
    if (tid < TB) { int tt = t0 + tid; if (tt >= cnt) tt = cnt - 1; stok[tid] = etok[e*256+tt]; }
    __syncthreads();
    float acc[TB][HT];
    #pragma unroll
    for (int j = 0; j < TB; j++)
        #pragma unroll
        for (int q = 0; q < HT; q++) acc[j][q] = 0.f;
    const float* w1e = w1 + (size_t)e * DD * HID;
    for (int dc = 0; dc < DD; dc += 64) {
        for (int i = tid; i < TB * 64; i += 128)
            fch[i/64][i%64] = feats[(size_t)stok[i/64] * DD + dc + i%64];
        __syncthreads();
        for (int dd = 0; dd < 64; dd++) {
            float wv[HT];
            const float* wrow = w1e + (size_t)(dc + dd) * HID + hid0;
            #pragma unroll
            for (int q = 0; q < HT; q++) wv[q] = wrow[q * 128];
            #pragma unroll
            for (int j = 0; j < TB; j++) {
                float f = fch[j][dd];
                #pragma unroll
                for (int q = 0; q < HT; q++) acc[j][q] += f * wv[q];
            }
        }
        __syncthreads();
    }
    float bv[HT];
    #pragma unroll
    for (int q = 0; q < HT; q++) bv[q] = b1[e * HID + hid0 + q * 128];
    for (int j = 0; j < TB; j++) {
        if (t0 + j >= cnt) break;
        size_t slot = (size_t)(e * 256 + t0 + j);
        #pragma unroll
        for (int q = 0; q < HT; q++)
            hbuf[slot * HID + hid0 + q * 128] = fmaxf(acc[j][q] + bv[q], 0.f);
    }
}

__global__ void moe_fc2(const float* __restrict__ hbuf, const float* __restrict__ w2,
                        const float* __restrict__ b2, const int* __restrict__ ecnt,
                        float* __restrict__ obuf) {
    constexpr int TB = 8, HT = 4;
    const int e = blockIdx.x, cnt = ecnt[e], t0 = blockIdx.z * TB;
    if (t0 >= cnt) return;
    const int tid = threadIdx.x, o0 = blockIdx.y * 512 + tid;
    __shared__ float hch[TB][64];
    float acc[TB][HT];
    #pragma unroll
    for (int j = 0; j < TB; j++)
        #pragma unroll
        for (int q = 0; q < HT; q++) acc[j][q] = 0.f;
    const float* w2e = w2 + (size_t)e * HID * OO;
    for (int hc = 0; hc < HID; hc += 64) {
        for (int i = tid; i < TB * 64; i += 128) {
            int j = i / 64, tt = t0 + j; if (tt >= cnt) tt = cnt - 1;
            hch[j][i%64] = hbuf[(size_t)(e * 256 + tt) * HID + hc + i%64];
        }
        __syncthreads();
        for (int dd = 0; dd < 64; dd++) {
            float wv[HT];
            const float* wrow = w2e + (size_t)(hc + dd) * OO + o0;
            #pragma unroll
            for (int q = 0; q < HT; q++) wv[q] = wrow[q * 128];
            #pragma unroll
            for (int j = 0; j < TB; j++) {
                float h = hch[j][dd];
                #pragma unroll
                for (int q = 0; q < HT; q++) acc[j][q] += h * wv[q];
            }
        }
        __syncthreads();
    }
    float bv[HT];
    #pragma unroll
    for (int q = 0; q < HT; q++) bv[q] = b2[e * OO + o0 + q * 128];
    for (int j = 0; j < TB; j++) {
        if (t0 + j >= cnt) break;
        size_t slot = (size_t)(e * 256 + t0 + j);
        #pragma unroll
        for (int q = 0; q < HT; q++)
            obuf[slot * OO + o0 + q * 128] = acc[j][q] + bv[q];
    }
}

__global__ void moe_combine(const float* __restrict__ obuf, const int* __restrict__ ecnt,
                            const float* __restrict__ egate, const int* __restrict__ etok,
                            float* __restrict__ y) {
    const int e = blockIdx.x >> 8, pos = blockIdx.x & 255;
    if (pos >= ecnt[e]) return;
    const int slot = e * 256 + pos, tid = threadIdx.x;
    const float* orow = obuf + (size_t)slot * OO;
    float v[4];
    #pragma unroll
    for (int q = 0; q < 4; q++) v[q] = orow[tid + q * 256];
    __shared__ float red[256];
    red[tid] = fmaxf(fmaxf(v[0], v[1]), fmaxf(v[2], v[3])); __syncthreads();
    for (int s = 128; s > 0; s >>= 1) { if (tid < s) red[tid] = fmaxf(red[tid], red[tid+s]); __syncthreads(); }
    float m = red[0]; __syncthreads();
    float ev[4];
    #pragma unroll
    for (int q = 0; q < 4; q++) ev[q] = expf(v[q] - m);
    red[tid] = ev[0] + ev[1] + ev[2] + ev[3]; __syncthreads();
    for (int s = 128; s > 0; s >>= 1) { if (tid < s) red[tid] += red[tid+s]; __syncthreads(); }
    float scale = egate[slot] / red[0];
    int b = etok[slot];
    #pragma unroll
    for (int q = 0; q < 4; q++)
        atomicAdd(&y[(size_t)b * OO + tid + q * 256], ev[q] * scale);
}

__global__ void zero_y(float* __restrict__ y) {
    int i = blockIdx.x * blockDim.x + threadIdx.x;
    if (i < NB * OO) y[i] = 0.f;
}

extern "C" void kernel_launch(void* const* d_in, const int* in_sizes, int n_in,
                              void* d_out, int out_size) {
    const float* x   = (const float*)d_in[0];
    const float* cw1 = (const float*)d_in[1];  const float* cb1 = (const float*)d_in[2];
    const float* cw2 = (const float*)d_in[3];  const float* cb2 = (const float*)d_in[4];
    const float* cw3 = (const float*)d_in[5];  const float* cb3 = (const float*)d_in[6];
    const float* cw4 = (const float*)d_in[7];  const float* cb4 = (const float*)d_in[8];
    const float* cw5 = (const float*)d_in[9];  const float* cb5 = (const float*)d_in[10];
    const float* w1  = (const float*)d_in[11]; const float* b1  = (const float*)d_in[12];
    const float* w2  = (const float*)d_in[13]; const float* b2  = (const float*)d_in[14];
    const float* wg  = (const float*)d_in[15];
    float* out = (float*)d_out;

    uint16_t *act2, *act3, *act4, *act5, *wt2, *wt3, *wt4, *wt5;
    float *prepool, *feats, *logits, *egate, *hbuf, *obuf;
    int *ecnt, *etok;
    cudaGetSymbolAddress((void**)&act2, g_act2);
    cudaGetSymbolAddress((void**)&act3, g_act3);
    cudaGetSymbolAddress((void**)&act4, g_act4);
    cudaGetSymbolAddress((void**)&act5, g_act5);
    cudaGetSymbolAddress((void**)&wt2, g_wt2);
    cudaGetSymbolAddress((void**)&wt3, g_wt3);
    cudaGetSymbolAddress((void**)&wt4, g_wt4);
    cudaGetSymbolAddress((void**)&wt5, g_wt5);
    cudaGetSymbolAddress((void**)&prepool, g_prepool);
    cudaGetSymbolAddress((void**)&feats, g_feats);
    cudaGetSymbolAddress((void**)&logits, g_logits);
    cudaGetSymbolAddress((void**)&ecnt, g_ecnt);
    cudaGetSymbolAddress((void**)&etok, g_etok);
    cudaGetSymbolAddress((void**)&egate, g_egate);
    cudaGetSymbolAddress((void**)&hbuf, g_h);
    cudaGetSymbolAddress((void**)&obuf, g_o);

    float* aux_ptr = (out_size > NB * OO) ? (out + NB * OO) : nullptr;

    zero_y<<<(NB * OO + 255) / 256, 256>>>(out);

    prep_w<<<(256 * 128 + 255) / 256, 256>>>(cw2, wt2, 128, 256);
    prep_w<<<(256 * 256 + 255) / 256, 256>>>(cw3, wt3, 256, 256);
    prep_w<<<(512 * 256 + 255) / 256, 256>>>(cw4, wt4, 256, 512);
    prep_w<<<(512 * 512 + 255) / 256, 256>>>(cw5, wt5, 512, 512);

    conv1_pool<<<dim3(256, 16, 4), 256>>>(x, cw1, cb1, act2);

    conv_mma<128, 32, 32, 256><<<dim3(2312, 2), 256>>>(act2, wt2, cb2, prepool);
    pool_to_act<<<(256*16*16*256 + 255)/256, 256>>>(prepool, act3, 32, 256);
    conv_mma<256, 16, 16, 256><<<dim3(648, 2), 256>>>(act3, wt3, cb3, prepool);
    pool_to_act<<<(256*8*8*256 + 255)/256, 256>>>(prepool, act4, 16, 256);
    conv_mma<256, 8, 8, 512><<<dim3(200, 4), 256>>>(act4, wt4, cb4, prepool);
    pool_to_act<<<(256*4*4*512 + 255)/256, 256>>>(prepool, act5, 8, 512);
    conv_mma<512, 4, 4, 512><<<dim3(72, 4), 256>>>(act5, wt5, cb5, prepool);
    pool_to_feats<<<(256*4*512 + 255)/256, 256>>>(prepool, feats);

    gate_logits<<<256, 128>>>(feats, wg, logits);
    gate_topk<<<1, 256>>>(logits, ecnt, etok, egate, aux_ptr);

    moe_fc1<<<dim3(16, 8, 32), 128>>>(feats, w1, b1, ecnt, etok, hbuf);
    moe_fc2<<<dim3(16, 2, 32), 128>>>(hbuf, w2, b2, ecnt, obuf);
    moe_combine<<<dim3(16 * 256), 256>>>(obuf, ecnt, egate, etok, out);
}